// round 1
// baseline (speedup 1.0000x reference)
#include <cuda_runtime.h>
#include <math.h>

#define Hh 12
#define Aa 16
#define Cc 768
#define HD 64
#define Bb 8
#define Nn 4096

// ---------------- device scratch (static, no allocation) ----------------
__device__ __align__(16) float g_q[(size_t)Bb*Nn*Cc];
__device__ __align__(16) float g_k[(size_t)Bb*Nn*Cc];
__device__ __align__(16) float g_v[(size_t)Bb*Nn*Cc];
__device__ __align__(16) float g_agent[(size_t)Bb*Aa*Cc];
__device__ __align__(16) float g_agentv[(size_t)Bb*Hh*Aa*HD];
__device__ float g_ab[Hh*Aa];

// ---------------- ab bias: separable bilinear-resize mean ----------------
// ab[h][a] = sum_{i,j} W[i]W[j] na[h,a,i,j] + mean_i ha[h,i,a] + mean_j wa[h,j,a]
__global__ void bias_ab_kernel(const float* __restrict__ na,
                               const float* __restrict__ ha,
                               const float* __restrict__ wa)
{
    int t = threadIdx.x;
    if (t >= Hh * Aa) return;
    int h = t >> 4, a = t & 15;

    float Wt[7];
#pragma unroll
    for (int i = 0; i < 7; i++) Wt[i] = 0.f;
    // jax.image.resize 'bilinear' 7->16: half-pixel centers, edge-renormalized
    for (int o = 0; o < 16; o++) {
        float x = (o + 0.5f) * (7.0f / 16.0f) - 0.5f;
        float fx = floorf(x);
        int i0 = (int)fx;
        float f = x - fx;
        if (i0 < 0)        Wt[0] += 1.f;
        else if (i0 >= 6)  Wt[6] += 1.f;
        else { Wt[i0] += 1.f - f; Wt[i0 + 1] += f; }
    }

    float s = 0.f;
    const float* np = na + (size_t)t * 49;
#pragma unroll
    for (int i = 0; i < 7; i++)
#pragma unroll
        for (int j = 0; j < 7; j++)
            s += Wt[i] * Wt[j] * np[i * 7 + j];

    float sh = 0.f, sw = 0.f;
#pragma unroll
    for (int i = 0; i < 16; i++) {
        sh += ha[(h * 16 + i) * 16 + a];  // (1,H,A,1,A)
        sw += wa[(h * 16 + i) * 16 + a];  // (1,H,1,A,A)
    }
    g_ab[t] = s * (1.f / 256.f) + (sh + sw) * (1.f / 16.f);
}

// ---------------- QKV GEMM: Y = X * W^T + b  (M=32768, N=768, K=768) ----
__global__ __launch_bounds__(256) void gemm_qkv(
    const float* __restrict__ X, const float* __restrict__ W,
    const float* __restrict__ bias, int sel)
{
    float* Y = (sel == 0) ? g_q : ((sel == 1) ? g_k : g_v);

    __shared__ float As[16][136];
    __shared__ float Bs[16][136];

    const int t = threadIdx.x;
    const int tx = t & 15, ty = t >> 4;
    const int rb = blockIdx.y, cb = blockIdx.x;
    const float* Xp = X + (size_t)rb * 128 * Cc;
    const float* Wp = W + (size_t)cb * 128 * Cc;

    float acc[8][8];
#pragma unroll
    for (int i = 0; i < 8; i++)
#pragma unroll
        for (int j = 0; j < 8; j++) acc[i][j] = 0.f;

    const int lrow = t >> 2;        // 0..63
    const int lk = (t & 3) * 4;     // 0,4,8,12

    for (int kt = 0; kt < Cc; kt += 16) {
#pragma unroll
        for (int p = 0; p < 2; p++) {
            int r = lrow + p * 64;
            float4 va = *(const float4*)(Xp + (size_t)r * Cc + kt + lk);
            As[lk + 0][r] = va.x; As[lk + 1][r] = va.y;
            As[lk + 2][r] = va.z; As[lk + 3][r] = va.w;
            float4 vb = *(const float4*)(Wp + (size_t)r * Cc + kt + lk);
            Bs[lk + 0][r] = vb.x; Bs[lk + 1][r] = vb.y;
            Bs[lk + 2][r] = vb.z; Bs[lk + 3][r] = vb.w;
        }
        __syncthreads();
#pragma unroll
        for (int kk = 0; kk < 16; kk++) {
            float4 a0 = *(const float4*)&As[kk][ty * 4];
            float4 a1 = *(const float4*)&As[kk][64 + ty * 4];
            float4 b0 = *(const float4*)&Bs[kk][tx * 4];
            float4 b1 = *(const float4*)&Bs[kk][64 + tx * 4];
            float av[8] = {a0.x, a0.y, a0.z, a0.w, a1.x, a1.y, a1.z, a1.w};
            float bv[8] = {b0.x, b0.y, b0.z, b0.w, b1.x, b1.y, b1.z, b1.w};
#pragma unroll
            for (int i = 0; i < 8; i++)
#pragma unroll
                for (int j = 0; j < 8; j++)
                    acc[i][j] += av[i] * bv[j];
        }
        __syncthreads();
    }

#pragma unroll
    for (int i = 0; i < 8; i++) {
        int row = rb * 128 + ((i < 4) ? (ty * 4 + i) : (64 + ty * 4 + i - 4));
#pragma unroll
        for (int jg = 0; jg < 2; jg++) {
            int col = cb * 128 + jg * 64 + tx * 4;
            float4 o;
            o.x = acc[i][jg * 4 + 0] + bias[col + 0];
            o.y = acc[i][jg * 4 + 1] + bias[col + 1];
            o.z = acc[i][jg * 4 + 2] + bias[col + 2];
            o.w = acc[i][jg * 4 + 3] + bias[col + 3];
            *(float4*)(&Y[(size_t)row * Cc + col]) = o;
        }
    }
}

// ---------------- agent pooling: mean over 256-row chunks of q ----------
__global__ void pool_agent(void)
{
    int b = blockIdx.x >> 4, a = blockIdx.x & 15;
    int c = threadIdx.x;
    const float* p = g_q + ((size_t)b * Nn + a * 256) * Cc + c;
    float s = 0.f;
#pragma unroll 8
    for (int i = 0; i < 256; i++) s += p[(size_t)i * Cc];
    g_agent[((size_t)b * Aa + a) * Cc + c] = s * (1.f / 256.f);
}

// ---------------- warp-group-of-16 reductions ----------------
__device__ __forceinline__ float rmax16(float v) {
    v = fmaxf(v, __shfl_xor_sync(0xffffffffu, v, 8));
    v = fmaxf(v, __shfl_xor_sync(0xffffffffu, v, 4));
    v = fmaxf(v, __shfl_xor_sync(0xffffffffu, v, 2));
    v = fmaxf(v, __shfl_xor_sync(0xffffffffu, v, 1));
    return v;
}
__device__ __forceinline__ float rsum16(float v) {
    v += __shfl_xor_sync(0xffffffffu, v, 8);
    v += __shfl_xor_sync(0xffffffffu, v, 4);
    v += __shfl_xor_sync(0xffffffffu, v, 2);
    v += __shfl_xor_sync(0xffffffffu, v, 1);
    return v;
}

// ---------------- stage 1: agents attend to keys (flash, 16 queries) ----
// One block per (b,h). pb bias is softmax-invariant -> omitted.
__global__ __launch_bounds__(256) void stage1(void)
{
    const int h = blockIdx.x, b = blockIdx.y;
    __shared__ float Ks[128][68];
    __shared__ float Vs[128][68];
    __shared__ float Ps[16][132];

    const int t = threadIdx.x;
    const int a = t >> 4, lx = t & 15;

    float4 qa[16];
    {
        const float* ap = g_agent + ((size_t)b * Aa + a) * Cc + h * HD;
#pragma unroll
        for (int i = 0; i < 16; i++) {
            float4 v = *(const float4*)(ap + i * 4);
            qa[i] = make_float4(v.x * 0.125f, v.y * 0.125f, v.z * 0.125f, v.w * 0.125f);
        }
    }

    float m_run = -1e30f, l_run = 0.f;
    float4 acc = make_float4(0.f, 0.f, 0.f, 0.f);
    const float* Kb = g_k + (size_t)b * Nn * Cc + h * HD;
    const float* Vb = g_v + (size_t)b * Nn * Cc + h * HD;

    for (int m0 = 0; m0 < Nn; m0 += 128) {
        __syncthreads();
#pragma unroll
        for (int u = 0; u < 8; u++) {
            int idx = t + u * 256;
            int r = idx >> 4, dq = idx & 15;
            ((float4*)&Ks[r][0])[dq] = *(const float4*)(Kb + (size_t)(m0 + r) * Cc + dq * 4);
            ((float4*)&Vs[r][0])[dq] = *(const float4*)(Vb + (size_t)(m0 + r) * Cc + dq * 4);
        }
        __syncthreads();

        float sv[8];
        float tmax = -1e30f;
#pragma unroll
        for (int jj = 0; jj < 8; jj++) {
            int j = lx + jj * 16;
            const float4* kr = (const float4*)&Ks[j][0];
            float4 s4 = make_float4(0.f, 0.f, 0.f, 0.f);
#pragma unroll
            for (int dq = 0; dq < 16; dq++) {
                float4 kv = kr[dq];
                s4.x += qa[dq].x * kv.x; s4.y += qa[dq].y * kv.y;
                s4.z += qa[dq].z * kv.z; s4.w += qa[dq].w * kv.w;
            }
            float s = (s4.x + s4.y) + (s4.z + s4.w);
            sv[jj] = s;
            tmax = fmaxf(tmax, s);
        }
        tmax = rmax16(tmax);
        float nm = fmaxf(m_run, tmax);
        float corr = __expf(m_run - nm);
        float ls = 0.f;
#pragma unroll
        for (int jj = 0; jj < 8; jj++) {
            float p = __expf(sv[jj] - nm);
            Ps[a][lx + jj * 16] = p;
            ls += p;
        }
        ls = rsum16(ls);
        l_run = l_run * corr + ls;
        m_run = nm;
        acc.x *= corr; acc.y *= corr; acc.z *= corr; acc.w *= corr;
        __syncwarp();
        for (int j = 0; j < 128; j++) {
            float p = Ps[a][j];
            float4 vv = ((const float4*)&Vs[j][0])[lx];
            acc.x += p * vv.x; acc.y += p * vv.y;
            acc.z += p * vv.z; acc.w += p * vv.w;
        }
    }
    float inv = 1.f / l_run;
    float4 o = make_float4(acc.x * inv, acc.y * inv, acc.z * inv, acc.w * inv);
    *(float4*)&g_agentv[(((size_t)b * Hh + h) * Aa + a) * HD + lx * 4] = o;
}

// ---------------- stage 2: queries attend to agents, write output -------
// grid (b=8, nchunk=16, headgroup=2), block 384 = 6 heads x 64 rows
__global__ __launch_bounds__(384) void stage2(float* __restrict__ out)
{
    const int b = blockIdx.x;
    const int hg = blockIdx.z;
    __shared__ float ahh[6 * 16 * 64];   // [hl][a][d]
    __shared__ float agv[6 * 16 * 64];   // [hl][a][d]

    const int t = threadIdx.x;
    const int hl = t % 6;
    const int h = hg * 6 + hl;
    const int rl = t / 6;   // 0..63

    for (int i = t; i < 6 * 16 * 64; i += 384) {
        int d = i & 63, a = (i >> 6) & 15, hh = i >> 10;
        int hglob = hg * 6 + hh;
        ahh[i] = g_agent[((size_t)b * Aa + a) * Cc + hglob * HD + d];
        agv[i] = g_agentv[(((size_t)b * Hh + hglob) * Aa + a) * HD + d];
    }
    __syncthreads();

    float abv[16];
#pragma unroll
    for (int a = 0; a < 16; a++) abv[a] = g_ab[h * 16 + a];

    const int r0 = blockIdx.y * 256;
    for (int it = 0; it < 4; it++) {
        int r = r0 + it * 64 + rl;
        const float* qp = g_q + ((size_t)b * Nn + r) * Cc + h * HD;
        float4 q[16];
#pragma unroll
        for (int dq = 0; dq < 16; dq++) q[dq] = *(const float4*)(qp + dq * 4);

        float s[16];
        float smax = -1e30f;
#pragma unroll
        for (int a = 0; a < 16; a++) {
            const float4* ap = (const float4*)&ahh[(hl * 16 + a) * 64];
            float4 s4 = make_float4(0.f, 0.f, 0.f, 0.f);
#pragma unroll
            for (int dq = 0; dq < 16; dq++) {
                float4 av = ap[dq];
                s4.x += q[dq].x * av.x; s4.y += q[dq].y * av.y;
                s4.z += q[dq].z * av.z; s4.w += q[dq].w * av.w;
            }
            float sc = ((s4.x + s4.y) + (s4.z + s4.w)) * 0.125f + abv[a];
            s[a] = sc;
            smax = fmaxf(smax, sc);
        }
        float ssum = 0.f;
#pragma unroll
        for (int a = 0; a < 16; a++) { s[a] = __expf(s[a] - smax); ssum += s[a]; }
        float inv = 1.f / ssum;

        float4 o[16];
#pragma unroll
        for (int dq = 0; dq < 16; dq++) o[dq] = make_float4(0.f, 0.f, 0.f, 0.f);
#pragma unroll
        for (int a = 0; a < 16; a++) {
            float p = s[a] * inv;
            const float4* vp = (const float4*)&agv[(hl * 16 + a) * 64];
#pragma unroll
            for (int dq = 0; dq < 16; dq++) {
                float4 av = vp[dq];
                o[dq].x += p * av.x; o[dq].y += p * av.y;
                o[dq].z += p * av.z; o[dq].w += p * av.w;
            }
        }
        float* op = out + ((size_t)b * Nn + r) * Cc + h * HD;
#pragma unroll
        for (int dq = 0; dq < 16; dq++) *(float4*)(op + dq * 4) = o[dq];
    }
}

// ---------------- launch ----------------
extern "C" void kernel_launch(void* const* d_in, const int* in_sizes, int n_in,
                              void* d_out, int out_size)
{
    const float* s1 = (const float*)d_in[0];
    const float* s2 = (const float*)d_in[1];
    const float* Wq = (const float*)d_in[2];
    const float* bq = (const float*)d_in[3];
    const float* Wk = (const float*)d_in[4];
    const float* bk = (const float*)d_in[5];
    const float* Wv = (const float*)d_in[6];
    const float* bv = (const float*)d_in[7];
    // d_in[8] = an_bias : unused (pb is softmax-invariant)
    const float* na = (const float*)d_in[9];
    // d_in[10]/[11] = ah_bias/aw_bias : unused (pb is softmax-invariant)
    const float* ha = (const float*)d_in[12];
    const float* wa = (const float*)d_in[13];
    float* out = (float*)d_out;

    bias_ab_kernel<<<1, 256>>>(na, ha, wa);

    dim3 gg(Cc / 128, (Bb * Nn) / 128);   // (6, 256)
    gemm_qkv<<<gg, 256>>>(s1, Wq, bq, 0);
    gemm_qkv<<<gg, 256>>>(s2, Wk, bk, 1);
    gemm_qkv<<<gg, 256>>>(s2, Wv, bv, 2);

    pool_agent<<<Bb * Aa, Cc>>>();
    stage1<<<dim3(Hh, Bb), 256>>>();
    stage2<<<dim3(Bb, 16, 2), 384>>>(out);
}

// round 5
// speedup vs baseline: 2.0127x; 2.0127x over previous
#include <cuda_runtime.h>
#include <cuda_bf16.h>
#include <math.h>
#include <stdint.h>

#define Hh 12
#define Aa 16
#define Cc 768
#define HD 64
#define Bb 8
#define Nn 4096

// ======================= helpers =======================
__device__ __forceinline__ uint32_t smem_u32(const void* p) {
    uint32_t a;
    asm("{ .reg .u64 t; cvta.to.shared.u64 t, %1; cvt.u32.u64 %0, t; }" : "=r"(a) : "l"(p));
    return a;
}

#define SMEM_SWIZZLE_128B(off) ((off) ^ (((off) >> 3) & 0x70))

__device__ __forceinline__ void ldsm4(uint32_t* r, uint32_t a) {
    asm volatile("ldmatrix.sync.aligned.m8n8.x4.shared.b16 {%0,%1,%2,%3}, [%4];"
                 : "=r"(r[0]), "=r"(r[1]), "=r"(r[2]), "=r"(r[3]) : "r"(a));
}
__device__ __forceinline__ void mma16816(float* c, const uint32_t* a, const uint32_t* b) {
    asm volatile(
        "mma.sync.aligned.m16n8k16.row.col.f32.bf16.bf16.f32 "
        "{%0,%1,%2,%3}, {%4,%5,%6,%7}, {%8,%9}, {%0,%1,%2,%3};"
        : "+f"(c[0]), "+f"(c[1]), "+f"(c[2]), "+f"(c[3])
        : "r"(a[0]), "r"(a[1]), "r"(a[2]), "r"(a[3]), "r"(b[0]), "r"(b[1]));
}

// ======================= device scratch =======================
__device__ __align__(16) float g_q[(size_t)Bb * Nn * Cc];
__device__ __align__(16) float g_k[(size_t)Bb * Nn * Cc];
__device__ __align__(16) float g_v[(size_t)Bb * Nn * Cc];
__device__ __align__(16) float g_agent[(size_t)Bb * Aa * Cc];
__device__ __align__(16) float g_agentv[(size_t)Bb * Hh * Aa * HD];
__device__ float g_ab[Hh * Aa];
__device__ __align__(16) __nv_bfloat16 g_w_hi[3 * Cc * Cc];
__device__ __align__(16) __nv_bfloat16 g_w_lo[3 * Cc * Cc];
#define NSPLIT 8
__device__ float g_p1m[NSPLIT * Bb * Hh * Aa];
__device__ float g_p1l[NSPLIT * Bb * Hh * Aa];
__device__ __align__(16) float g_p1acc[(size_t)NSPLIT * Bb * Hh * Aa * HD];

// ======================= ab bias =======================
__global__ void bias_ab_kernel(const float* __restrict__ na,
                               const float* __restrict__ ha,
                               const float* __restrict__ wa)
{
    int t = threadIdx.x;
    if (t >= Hh * Aa) return;
    int h = t >> 4, a = t & 15;

    float Wt[7];
#pragma unroll
    for (int i = 0; i < 7; i++) Wt[i] = 0.f;
    for (int o = 0; o < 16; o++) {
        float x = (o + 0.5f) * (7.0f / 16.0f) - 0.5f;
        float fx = floorf(x);
        int i0 = (int)fx;
        float f = x - fx;
        if (i0 < 0)       Wt[0] += 1.f;
        else if (i0 >= 6) Wt[6] += 1.f;
        else { Wt[i0] += 1.f - f; Wt[i0 + 1] += f; }
    }
    float s = 0.f;
    const float* np = na + (size_t)t * 49;
#pragma unroll
    for (int i = 0; i < 7; i++)
#pragma unroll
        for (int j = 0; j < 7; j++)
            s += Wt[i] * Wt[j] * np[i * 7 + j];

    float sh = 0.f, sw = 0.f;
#pragma unroll
    for (int i = 0; i < 16; i++) {
        sh += ha[(h * 16 + i) * 16 + a];
        sw += wa[(h * 16 + i) * 16 + a];
    }
    g_ab[t] = s * (1.f / 256.f) + (sh + sw) * (1.f / 16.f);
}

// ======================= weight pre-split to bf16 hi/lo =======================
__global__ void convert_w(const float* __restrict__ Wq,
                          const float* __restrict__ Wk,
                          const float* __restrict__ Wv)
{
    int idx = blockIdx.x * 256 + threadIdx.x;
    int w = idx / 147456;
    int r = idx - w * 147456;
    const float* src = (w == 0) ? Wq : ((w == 1) ? Wk : Wv);
    float4 x = *(const float4*)(src + (size_t)r * 4);
    __nv_bfloat162 h01 = __floats2bfloat162_rn(x.x, x.y);
    __nv_bfloat162 h23 = __floats2bfloat162_rn(x.z, x.w);
    uint32_t u01 = *reinterpret_cast<uint32_t*>(&h01);
    uint32_t u23 = *reinterpret_cast<uint32_t*>(&h23);
    float lx = x.x - __uint_as_float(u01 << 16);
    float ly = x.y - __uint_as_float(u01 & 0xffff0000u);
    float lz = x.z - __uint_as_float(u23 << 16);
    float lw = x.w - __uint_as_float(u23 & 0xffff0000u);
    __nv_bfloat162 l01 = __floats2bfloat162_rn(lx, ly);
    __nv_bfloat162 l23 = __floats2bfloat162_rn(lz, lw);
    *(uint2*)&g_w_hi[(size_t)idx * 4] = make_uint2(u01, u23);
    *(uint2*)&g_w_lo[(size_t)idx * 4] =
        make_uint2(*reinterpret_cast<uint32_t*>(&l01), *reinterpret_cast<uint32_t*>(&l23));
}

// ======================= HMMA GEMM =======================
// Y[32768x768] = X * W^T + bias, via bf16 hi/lo 3-pass split.
// CTA tile 128x128, warp tile 64x32, K-chunk 64, double-buffered SW128 SMEM.
// stage layout: A_hi 16K | A_lo 16K | B_hi 16K | B_lo 16K
// NOTE: weights/outputs resolved from __device__ globals INSIDE device code
// (host-side references to __device__ symbols read the host shadow via ATS!)
#define GS_STAGE 65536
#define GS_TOTAL (2 * GS_STAGE)

__global__ __launch_bounds__(256, 1) void gemm_hmma(
    const float* __restrict__ X, const float* __restrict__ bias, int sel)
{
    extern __shared__ char smem[];
    const uint32_t sb = smem_u32(smem);
    const int t = threadIdx.x, lane = t & 31, wid = t >> 5;
    const int rb = blockIdx.y, cb = blockIdx.x;

    const __nv_bfloat16* WH = g_w_hi + (size_t)sel * Cc * Cc;
    const __nv_bfloat16* WL = g_w_lo + (size_t)sel * Cc * Cc;
    float* Y = (sel == 0) ? g_q : ((sel == 1) ? g_k : g_v);

    const float* Xp = X + (size_t)rb * 128 * Cc;
    const __nv_bfloat16* WHp = WH + (size_t)cb * 128 * Cc;
    const __nv_bfloat16* WLp = WL + (size_t)cb * 128 * Cc;

    const int m_warp = (wid >> 2) * 64, n_warp = (wid & 3) * 32;

    // ldmatrix lane addressing (all NON-trans):
    const int rlA = (lane & 7) | (((lane >> 3) & 1) << 3);
    const int chA = lane >> 4;                 // +16B => k+8
    const int rlB = (lane & 7) | ((lane >> 4) << 3);
    const int chB = (lane >> 3) & 1;           // +16B => k+8
    uint32_t aRow[4];
#pragma unroll
    for (int mi = 0; mi < 4; mi++)
        aRow[mi] = (uint32_t)(m_warp + mi * 16 + rlA) * 128;
    uint32_t bRow[2];
#pragma unroll
    for (int j = 0; j < 2; j++)
        bRow[j] = (uint32_t)(n_warp + j * 16 + rlB) * 128;
    const uint32_t aXor = (uint32_t)(rlA & 7) << 4;
    const uint32_t bXor = (uint32_t)(rlB & 7) << 4;

    float acc[4][4][4];
#pragma unroll
    for (int i = 0; i < 4; i++)
#pragma unroll
        for (int j = 0; j < 4; j++)
#pragma unroll
            for (int r = 0; r < 4; r++) acc[i][j][r] = 0.f;

    float4 apre[8];
    uint4 bhp[4], blp[4];
    // prologue: load chunk 0
#pragma unroll
    for (int i = 0; i < 8; i++) {
        int u = t + (i << 8);
        int row = u >> 4, pos = u & 15;
        apre[i] = *(const float4*)(Xp + (size_t)row * Cc + pos * 4);
    }
#pragma unroll
    for (int i = 0; i < 4; i++) {
        int u = t + (i << 8);
        int row = u >> 3, pos = u & 7;
        bhp[i] = *(const uint4*)(WHp + (size_t)row * Cc + pos * 8);
        blp[i] = *(const uint4*)(WLp + (size_t)row * Cc + pos * 8);
    }

    for (int c = 0; c < 12; c++) {
        char* st = smem + (c & 1) * GS_STAGE;
        const uint32_t stb = sb + (c & 1) * GS_STAGE;
        // ---- STS phase: convert A fp32 -> hi/lo, copy B
#pragma unroll
        for (int i = 0; i < 8; i++) {
            int u = t + (i << 8);
            int row = u >> 4, pos = u & 15;
            __nv_bfloat162 h01 = __floats2bfloat162_rn(apre[i].x, apre[i].y);
            __nv_bfloat162 h23 = __floats2bfloat162_rn(apre[i].z, apre[i].w);
            uint32_t u01 = *reinterpret_cast<uint32_t*>(&h01);
            uint32_t u23 = *reinterpret_cast<uint32_t*>(&h23);
            float lx = apre[i].x - __uint_as_float(u01 << 16);
            float ly = apre[i].y - __uint_as_float(u01 & 0xffff0000u);
            float lz = apre[i].z - __uint_as_float(u23 << 16);
            float lw = apre[i].w - __uint_as_float(u23 & 0xffff0000u);
            __nv_bfloat162 l01 = __floats2bfloat162_rn(lx, ly);
            __nv_bfloat162 l23 = __floats2bfloat162_rn(lz, lw);
            uint32_t off = SMEM_SWIZZLE_128B((uint32_t)(row * 128 + pos * 8));
            *(uint2*)(st + off) = make_uint2(u01, u23);
            *(uint2*)(st + 16384 + off) =
                make_uint2(*reinterpret_cast<uint32_t*>(&l01), *reinterpret_cast<uint32_t*>(&l23));
        }
#pragma unroll
        for (int i = 0; i < 4; i++) {
            int u = t + (i << 8);
            int row = u >> 3, pos = u & 7;
            uint32_t off = SMEM_SWIZZLE_128B((uint32_t)(row * 128 + pos * 16));
            *(uint4*)(st + 32768 + off) = bhp[i];
            *(uint4*)(st + 49152 + off) = blp[i];
        }
        __syncthreads();
        // ---- prefetch next chunk (LDGs in flight during compute)
        if (c < 11) {
            const int kt = (c + 1) * 64;
#pragma unroll
            for (int i = 0; i < 8; i++) {
                int u = t + (i << 8);
                int row = u >> 4, pos = u & 15;
                apre[i] = *(const float4*)(Xp + (size_t)row * Cc + kt + pos * 4);
            }
#pragma unroll
            for (int i = 0; i < 4; i++) {
                int u = t + (i << 8);
                int row = u >> 3, pos = u & 7;
                bhp[i] = *(const uint4*)(WHp + (size_t)row * Cc + kt + pos * 8);
                blp[i] = *(const uint4*)(WLp + (size_t)row * Cc + kt + pos * 8);
            }
        }
        // ---- compute: 4 k-steps of 16
        const uint32_t sAh = stb, sAl = stb + 16384, sBh = stb + 32768, sBl = stb + 49152;
#pragma unroll
        for (int ks = 0; ks < 4; ks++) {
            const uint32_t ca = ((uint32_t)(ks * 32 + chA * 16)) ^ aXor;
            const uint32_t cbb = ((uint32_t)(ks * 32 + chB * 16)) ^ bXor;
            uint32_t Ah[4][4], Al[4][4], Bh[2][4], Bl[2][4];
#pragma unroll
            for (int mi = 0; mi < 4; mi++) {
                ldsm4(Ah[mi], sAh + aRow[mi] + ca);
                ldsm4(Al[mi], sAl + aRow[mi] + ca);
            }
#pragma unroll
            for (int j = 0; j < 2; j++) {
                ldsm4(Bh[j], sBh + bRow[j] + cbb);
                ldsm4(Bl[j], sBl + bRow[j] + cbb);
            }
#pragma unroll
            for (int mi = 0; mi < 4; mi++)
#pragma unroll
                for (int nj = 0; nj < 4; nj++) {
                    const uint32_t* bh = &Bh[nj >> 1][(nj & 1) * 2];
                    const uint32_t* bl = &Bl[nj >> 1][(nj & 1) * 2];
                    mma16816(acc[mi][nj], Ah[mi], bh);
                    mma16816(acc[mi][nj], Ah[mi], bl);
                    mma16816(acc[mi][nj], Al[mi], bh);
                }
        }
        __syncthreads();
    }

    // ---- epilogue: bias + store
#pragma unroll
    for (int mi = 0; mi < 4; mi++) {
        int r0 = rb * 128 + m_warp + mi * 16 + (lane >> 2);
#pragma unroll
        for (int nj = 0; nj < 4; nj++) {
            int gc = cb * 128 + n_warp + nj * 8 + (lane & 3) * 2;
            float b0 = bias[gc], b1 = bias[gc + 1];
            float2 o0 = make_float2(acc[mi][nj][0] + b0, acc[mi][nj][1] + b1);
            float2 o1 = make_float2(acc[mi][nj][2] + b0, acc[mi][nj][3] + b1);
            *(float2*)(Y + (size_t)r0 * Cc + gc) = o0;
            *(float2*)(Y + (size_t)(r0 + 8) * Cc + gc) = o1;
        }
    }
}

// ======================= agent pooling =======================
__global__ void pool_agent(void)
{
    int b = blockIdx.x >> 4, a = blockIdx.x & 15;
    int c = threadIdx.x;
    const float* p = g_q + ((size_t)b * Nn + a * 256) * Cc + c;
    float s = 0.f;
#pragma unroll 8
    for (int i = 0; i < 256; i++) s += p[(size_t)i * Cc];
    g_agent[((size_t)b * Aa + a) * Cc + c] = s * (1.f / 256.f);
}

// ======================= group-of-16 reductions =======================
__device__ __forceinline__ float rmax16(float v) {
    v = fmaxf(v, __shfl_xor_sync(0xffffffffu, v, 8));
    v = fmaxf(v, __shfl_xor_sync(0xffffffffu, v, 4));
    v = fmaxf(v, __shfl_xor_sync(0xffffffffu, v, 2));
    v = fmaxf(v, __shfl_xor_sync(0xffffffffu, v, 1));
    return v;
}
__device__ __forceinline__ float rsum16(float v) {
    v += __shfl_xor_sync(0xffffffffu, v, 8);
    v += __shfl_xor_sync(0xffffffffu, v, 4);
    v += __shfl_xor_sync(0xffffffffu, v, 2);
    v += __shfl_xor_sync(0xffffffffu, v, 1);
    return v;
}

// ======================= stage 1: split-KV flash (agents -> keys) ========
__global__ __launch_bounds__(256) void stage1(void)
{
    const int h = blockIdx.x, b = blockIdx.y, sp = blockIdx.z;
    __shared__ float Ks[128][68];
    __shared__ float Vs[128][68];
    __shared__ float Ps[16][132];

    const int t = threadIdx.x;
    const int a = t >> 4, lx = t & 15;

    float4 qa[16];
    {
        const float* ap = g_agent + ((size_t)b * Aa + a) * Cc + h * HD;
#pragma unroll
        for (int i = 0; i < 16; i++) {
            float4 v = *(const float4*)(ap + i * 4);
            qa[i] = make_float4(v.x * 0.125f, v.y * 0.125f, v.z * 0.125f, v.w * 0.125f);
        }
    }

    float m_run = -1e30f, l_run = 0.f;
    float4 acc = make_float4(0.f, 0.f, 0.f, 0.f);
    const float* Kb = g_k + (size_t)b * Nn * Cc + h * HD;
    const float* Vb = g_v + (size_t)b * Nn * Cc + h * HD;

    const int m_beg = sp * (Nn / NSPLIT);
    for (int m0 = m_beg; m0 < m_beg + Nn / NSPLIT; m0 += 128) {
        __syncthreads();
#pragma unroll
        for (int u = 0; u < 8; u++) {
            int idx = t + u * 256;
            int r = idx >> 4, dq = idx & 15;
            ((float4*)&Ks[r][0])[dq] = *(const float4*)(Kb + (size_t)(m0 + r) * Cc + dq * 4);
            ((float4*)&Vs[r][0])[dq] = *(const float4*)(Vb + (size_t)(m0 + r) * Cc + dq * 4);
        }
        __syncthreads();

        float sv[8];
        float tmax = -1e30f;
#pragma unroll
        for (int jj = 0; jj < 8; jj++) {
            int j = lx + jj * 16;
            const float4* kr = (const float4*)&Ks[j][0];
            float4 s4 = make_float4(0.f, 0.f, 0.f, 0.f);
#pragma unroll
            for (int dq = 0; dq < 16; dq++) {
                float4 kv = kr[dq];
                s4.x += qa[dq].x * kv.x; s4.y += qa[dq].y * kv.y;
                s4.z += qa[dq].z * kv.z; s4.w += qa[dq].w * kv.w;
            }
            float s = (s4.x + s4.y) + (s4.z + s4.w);
            sv[jj] = s;
            tmax = fmaxf(tmax, s);
        }
        tmax = rmax16(tmax);
        float nm = fmaxf(m_run, tmax);
        float corr = __expf(m_run - nm);
        float ls = 0.f;
#pragma unroll
        for (int jj = 0; jj < 8; jj++) {
            float p = __expf(sv[jj] - nm);
            Ps[a][lx + jj * 16] = p;
            ls += p;
        }
        ls = rsum16(ls);
        l_run = l_run * corr + ls;
        m_run = nm;
        acc.x *= corr; acc.y *= corr; acc.z *= corr; acc.w *= corr;
        __syncwarp();
        for (int j = 0; j < 128; j++) {
            float p = Ps[a][j];
            float4 vv = ((const float4*)&Vs[j][0])[lx];
            acc.x += p * vv.x; acc.y += p * vv.y;
            acc.z += p * vv.z; acc.w += p * vv.w;
        }
    }
    const int pi = ((sp * Bb + b) * Hh + h) * Aa + a;
    if (lx == 0) { g_p1m[pi] = m_run; g_p1l[pi] = l_run; }
    *(float4*)&g_p1acc[(size_t)pi * HD + lx * 4] = acc;
}

__global__ void stage1_merge(void)
{
    const int bh = blockIdx.x;
    const int b = bh / Hh, h = bh % Hh;
    const int t = threadIdx.x;
    const int a = t >> 4, lx = t & 15;

    float ms[NSPLIT];
    float gm = -1e30f;
#pragma unroll
    for (int s = 0; s < NSPLIT; s++) {
        ms[s] = g_p1m[((s * Bb + b) * Hh + h) * Aa + a];
        gm = fmaxf(gm, ms[s]);
    }
    float L = 0.f;
    float4 acc = make_float4(0.f, 0.f, 0.f, 0.f);
#pragma unroll
    for (int s = 0; s < NSPLIT; s++) {
        int pi = ((s * Bb + b) * Hh + h) * Aa + a;
        float w = __expf(ms[s] - gm);
        L += g_p1l[pi] * w;
        float4 p = *(const float4*)&g_p1acc[(size_t)pi * HD + lx * 4];
        acc.x += w * p.x; acc.y += w * p.y; acc.z += w * p.z; acc.w += w * p.w;
    }
    float inv = 1.f / L;
    float4 o = make_float4(acc.x * inv, acc.y * inv, acc.z * inv, acc.w * inv);
    *(float4*)&g_agentv[(((size_t)b * Hh + h) * Aa + a) * HD + lx * 4] = o;
}

// ======================= stage 2 =======================
__global__ __launch_bounds__(384) void stage2(float* __restrict__ out)
{
    const int b = blockIdx.x;
    const int hg = blockIdx.z;
    __shared__ float ahh[6 * 16 * 64];
    __shared__ float agv[6 * 16 * 64];

    const int t = threadIdx.x;
    const int hl = t % 6;
    const int h = hg * 6 + hl;
    const int rl = t / 6;

    for (int i = t; i < 6 * 16 * 64; i += 384) {
        int d = i & 63, a = (i >> 6) & 15, hh = i >> 10;
        int hglob = hg * 6 + hh;
        ahh[i] = g_agent[((size_t)b * Aa + a) * Cc + hglob * HD + d];
        agv[i] = g_agentv[(((size_t)b * Hh + hglob) * Aa + a) * HD + d];
    }
    __syncthreads();

    float abv[16];
#pragma unroll
    for (int a = 0; a < 16; a++) abv[a] = g_ab[h * 16 + a];

    const int r0 = blockIdx.y * 256;
    for (int it = 0; it < 4; it++) {
        int r = r0 + it * 64 + rl;
        const float* qp = g_q + ((size_t)b * Nn + r) * Cc + h * HD;
        float4 q[16];
#pragma unroll
        for (int dq = 0; dq < 16; dq++) q[dq] = *(const float4*)(qp + dq * 4);

        float s[16];
        float smax = -1e30f;
#pragma unroll
        for (int a = 0; a < 16; a++) {
            const float4* ap = (const float4*)&ahh[(hl * 16 + a) * 64];
            float4 s4 = make_float4(0.f, 0.f, 0.f, 0.f);
#pragma unroll
            for (int dq = 0; dq < 16; dq++) {
                float4 av = ap[dq];
                s4.x += q[dq].x * av.x; s4.y += q[dq].y * av.y;
                s4.z += q[dq].z * av.z; s4.w += q[dq].w * av.w;
            }
            float sc = ((s4.x + s4.y) + (s4.z + s4.w)) * 0.125f + abv[a];
            s[a] = sc;
            smax = fmaxf(smax, sc);
        }
        float ssum = 0.f;
#pragma unroll
        for (int a = 0; a < 16; a++) { s[a] = __expf(s[a] - smax); ssum += s[a]; }
        float inv = 1.f / ssum;

        float4 o[16];
#pragma unroll
        for (int dq = 0; dq < 16; dq++) o[dq] = make_float4(0.f, 0.f, 0.f, 0.f);
#pragma unroll
        for (int a = 0; a < 16; a++) {
            float p = s[a] * inv;
            const float4* vp = (const float4*)&agv[(hl * 16 + a) * 64];
#pragma unroll
            for (int dq = 0; dq < 16; dq++) {
                float4 av = vp[dq];
                o[dq].x += p * av.x; o[dq].y += p * av.y;
                o[dq].z += p * av.z; o[dq].w += p * av.w;
            }
        }
        float* op = out + ((size_t)b * Nn + r) * Cc + h * HD;
#pragma unroll
        for (int dq = 0; dq < 16; dq++) *(float4*)(op + dq * 4) = o[dq];
    }
}

// ======================= launch =======================
extern "C" void kernel_launch(void* const* d_in, const int* in_sizes, int n_in,
                              void* d_out, int out_size)
{
    const float* s1 = (const float*)d_in[0];
    const float* s2 = (const float*)d_in[1];
    const float* Wq = (const float*)d_in[2];
    const float* bq = (const float*)d_in[3];
    const float* Wk = (const float*)d_in[4];
    const float* bk = (const float*)d_in[5];
    const float* Wv = (const float*)d_in[6];
    const float* bv = (const float*)d_in[7];
    const float* na = (const float*)d_in[9];
    const float* ha = (const float*)d_in[12];
    const float* wa = (const float*)d_in[13];
    float* out = (float*)d_out;

    cudaFuncSetAttribute(gemm_hmma, cudaFuncAttributeMaxDynamicSharedMemorySize, GS_TOTAL);

    bias_ab_kernel<<<1, 256>>>(na, ha, wa);
    convert_w<<<1728, 256>>>(Wq, Wk, Wv);

    dim3 gg(Cc / 128, (Bb * Nn) / 128);   // (6, 256)
    gemm_hmma<<<gg, 256, GS_TOTAL>>>(s1, bq, 0);
    gemm_hmma<<<gg, 256, GS_TOTAL>>>(s2, bk, 1);
    gemm_hmma<<<gg, 256, GS_TOTAL>>>(s2, bv, 2);

    pool_agent<<<Bb * Aa, Cc>>>();
    stage1<<<dim3(Hh, Bb, NSPLIT), 256>>>();
    stage1_merge<<<Bb * Hh, 256>>>();
    stage2<<<dim3(Bb, 16, 2), 384>>>(out);
}

// round 6
// speedup vs baseline: 2.1648x; 1.0756x over previous
#include <cuda_runtime.h>
#include <cuda_bf16.h>
#include <math.h>
#include <stdint.h>

#define Hh 12
#define Aa 16
#define Cc 768
#define HD 64
#define Bb 8
#define Nn 4096

// ======================= helpers =======================
__device__ __forceinline__ uint32_t smem_u32(const void* p) {
    uint32_t a;
    asm("{ .reg .u64 t; cvta.to.shared.u64 t, %1; cvt.u32.u64 %0, t; }" : "=r"(a) : "l"(p));
    return a;
}

#define SMEM_SWIZZLE_128B(off) ((off) ^ (((off) >> 3) & 0x70))

__device__ __forceinline__ void ldsm4(uint32_t* r, uint32_t a) {
    asm volatile("ldmatrix.sync.aligned.m8n8.x4.shared.b16 {%0,%1,%2,%3}, [%4];"
                 : "=r"(r[0]), "=r"(r[1]), "=r"(r[2]), "=r"(r[3]) : "r"(a));
}
__device__ __forceinline__ void mma16816(float* c, const uint32_t* a, const uint32_t* b) {
    asm volatile(
        "mma.sync.aligned.m16n8k16.row.col.f32.bf16.bf16.f32 "
        "{%0,%1,%2,%3}, {%4,%5,%6,%7}, {%8,%9}, {%0,%1,%2,%3};"
        : "+f"(c[0]), "+f"(c[1]), "+f"(c[2]), "+f"(c[3])
        : "r"(a[0]), "r"(a[1]), "r"(a[2]), "r"(a[3]), "r"(b[0]), "r"(b[1]));
}
__device__ __forceinline__ void cp16(uint32_t dst, const void* src) {
    asm volatile("cp.async.cg.shared.global [%0], [%1], 16;" :: "r"(dst), "l"(src));
}
#define CP_COMMIT() asm volatile("cp.async.commit_group;" ::: "memory")
#define CP_WAIT(n)  asm volatile("cp.async.wait_group %0;" :: "n"(n) : "memory")

// ======================= device scratch =======================
__device__ __align__(16) float g_q[(size_t)Bb * Nn * Cc];
__device__ __align__(16) float g_k[(size_t)Bb * Nn * Cc];
__device__ __align__(16) float g_v[(size_t)Bb * Nn * Cc];
__device__ __align__(16) float g_agent[(size_t)Bb * Aa * Cc];
__device__ __align__(16) float g_agentv[(size_t)Bb * Hh * Aa * HD];
__device__ float g_ab[Hh * Aa];
__device__ __align__(16) __nv_bfloat16 g_w_hi[3 * Cc * Cc];
__device__ __align__(16) __nv_bfloat16 g_w_lo[3 * Cc * Cc];
// pre-split activations (bf16 hi/lo)
__device__ __align__(16) __nv_bfloat16 g_x1h[(size_t)Bb * Nn * Cc];
__device__ __align__(16) __nv_bfloat16 g_x1l[(size_t)Bb * Nn * Cc];
__device__ __align__(16) __nv_bfloat16 g_x2h[(size_t)Bb * Nn * Cc];
__device__ __align__(16) __nv_bfloat16 g_x2l[(size_t)Bb * Nn * Cc];
#define NSPLIT 8
__device__ float g_p1m[NSPLIT * Bb * Hh * Aa];
__device__ float g_p1l[NSPLIT * Bb * Hh * Aa];
__device__ __align__(16) float g_p1acc[(size_t)NSPLIT * Bb * Hh * Aa * HD];

// ======================= ab bias =======================
__global__ void bias_ab_kernel(const float* __restrict__ na,
                               const float* __restrict__ ha,
                               const float* __restrict__ wa)
{
    int t = threadIdx.x;
    if (t >= Hh * Aa) return;
    int h = t >> 4, a = t & 15;

    float Wt[7];
#pragma unroll
    for (int i = 0; i < 7; i++) Wt[i] = 0.f;
    for (int o = 0; o < 16; o++) {
        float x = (o + 0.5f) * (7.0f / 16.0f) - 0.5f;
        float fx = floorf(x);
        int i0 = (int)fx;
        float f = x - fx;
        if (i0 < 0)       Wt[0] += 1.f;
        else if (i0 >= 6) Wt[6] += 1.f;
        else { Wt[i0] += 1.f - f; Wt[i0 + 1] += f; }
    }
    float s = 0.f;
    const float* np = na + (size_t)t * 49;
#pragma unroll
    for (int i = 0; i < 7; i++)
#pragma unroll
        for (int j = 0; j < 7; j++)
            s += Wt[i] * Wt[j] * np[i * 7 + j];

    float sh = 0.f, sw = 0.f;
#pragma unroll
    for (int i = 0; i < 16; i++) {
        sh += ha[(h * 16 + i) * 16 + a];
        sw += wa[(h * 16 + i) * 16 + a];
    }
    g_ab[t] = s * (1.f / 256.f) + (sh + sw) * (1.f / 16.f);
}

// ======================= fp32 -> bf16 hi/lo split helpers ===============
__device__ __forceinline__ void split4(float4 x, uint2& hi, uint2& lo) {
    __nv_bfloat162 h01 = __floats2bfloat162_rn(x.x, x.y);
    __nv_bfloat162 h23 = __floats2bfloat162_rn(x.z, x.w);
    uint32_t u01 = *reinterpret_cast<uint32_t*>(&h01);
    uint32_t u23 = *reinterpret_cast<uint32_t*>(&h23);
    float lx = x.x - __uint_as_float(u01 << 16);
    float ly = x.y - __uint_as_float(u01 & 0xffff0000u);
    float lz = x.z - __uint_as_float(u23 << 16);
    float lw = x.w - __uint_as_float(u23 & 0xffff0000u);
    __nv_bfloat162 l01 = __floats2bfloat162_rn(lx, ly);
    __nv_bfloat162 l23 = __floats2bfloat162_rn(lz, lw);
    hi = make_uint2(u01, u23);
    lo = make_uint2(*reinterpret_cast<uint32_t*>(&l01), *reinterpret_cast<uint32_t*>(&l23));
}

// weights: 3*768*768/4 = 442368 float4; grid 1728 x 256
__global__ void convert_w(const float* __restrict__ Wq,
                          const float* __restrict__ Wk,
                          const float* __restrict__ Wv)
{
    int idx = blockIdx.x * 256 + threadIdx.x;
    int w = idx / 147456;
    int r = idx - w * 147456;
    const float* src = (w == 0) ? Wq : ((w == 1) ? Wk : Wv);
    uint2 hi, lo;
    split4(*(const float4*)(src + (size_t)r * 4), hi, lo);
    *(uint2*)&g_w_hi[(size_t)idx * 4] = hi;
    *(uint2*)&g_w_lo[(size_t)idx * 4] = lo;
}

// activations: 2 * 8*4096*768/4 = 12,582,912 float4; each thread does 4.
// grid 12288 x 256
__global__ void presplit_x(const float* __restrict__ s1, const float* __restrict__ s2)
{
    const size_t PER = (size_t)Bb * Nn * Cc / 4;   // 6291456 float4 per tensor
    size_t base = (size_t)blockIdx.x * 1024 + threadIdx.x;
#pragma unroll
    for (int i = 0; i < 4; i++) {
        size_t idx = base + (size_t)i * 256;
        const float* src;
        __nv_bfloat16 *dh, *dl;
        size_t r;
        if (idx < PER) { src = s1; dh = g_x1h; dl = g_x1l; r = idx; }
        else           { src = s2; dh = g_x2h; dl = g_x2l; r = idx - PER; }
        uint2 hi, lo;
        split4(*(const float4*)(src + r * 4), hi, lo);
        *(uint2*)&dh[r * 4] = hi;
        *(uint2*)&dl[r * 4] = lo;
    }
}

// ======================= HMMA GEMM (cp.async, all-bf16 operands) ========
// Y = X * W^T + bias. CTA tile 128x128, warp tile 64x32, K-chunk 64,
// 2-stage cp.async pipeline. Stage: Ahi 16K | Alo 16K | Bhi 16K | Blo 16K.
// grid (6, 256, 3): z selects q/k/v.
#define GS_STAGE 65536
#define GS_TOTAL (2 * GS_STAGE)

__global__ __launch_bounds__(256, 1) void gemm_hmma(
    const float* __restrict__ bq, const float* __restrict__ bk,
    const float* __restrict__ bv)
{
    extern __shared__ char smem[];
    const uint32_t sb = smem_u32(smem);
    const int t = threadIdx.x, lane = t & 31, wid = t >> 5;
    const int rb = blockIdx.y, cb = blockIdx.x, sel = blockIdx.z;

    const __nv_bfloat16* XH = (sel == 0) ? g_x1h : g_x2h;
    const __nv_bfloat16* XL = (sel == 0) ? g_x1l : g_x2l;
    const __nv_bfloat16* WH = g_w_hi + (size_t)sel * Cc * Cc;
    const __nv_bfloat16* WL = g_w_lo + (size_t)sel * Cc * Cc;
    float* Y = (sel == 0) ? g_q : ((sel == 1) ? g_k : g_v);
    const float* bias = (sel == 0) ? bq : ((sel == 1) ? bk : bv);

    const __nv_bfloat16* AHp = XH + (size_t)rb * 128 * Cc;
    const __nv_bfloat16* ALp = XL + (size_t)rb * 128 * Cc;
    const __nv_bfloat16* BHp = WH + (size_t)cb * 128 * Cc;
    const __nv_bfloat16* BLp = WL + (size_t)cb * 128 * Cc;

    // copy-lane mapping: 1024 granules (16B) per array per chunk; 4 per thread
    const int crow = t >> 3, cpos = t & 7;   // row 0..31 (+32*i), pos 0..7
    const uint32_t coff0 = SMEM_SWIZZLE_128B((uint32_t)(crow * 128 + cpos * 16));

    const int m_warp = (wid >> 2) * 64, n_warp = (wid & 3) * 32;
    const int rlA = (lane & 7) | (((lane >> 3) & 1) << 3);
    const int chA = lane >> 4;
    const int rlB = (lane & 7) | ((lane >> 4) << 3);
    const int chB = (lane >> 3) & 1;
    uint32_t aRow[4];
#pragma unroll
    for (int mi = 0; mi < 4; mi++)
        aRow[mi] = (uint32_t)(m_warp + mi * 16 + rlA) * 128;
    uint32_t bRow[2];
#pragma unroll
    for (int j = 0; j < 2; j++)
        bRow[j] = (uint32_t)(n_warp + j * 16 + rlB) * 128;
    const uint32_t aXor = (uint32_t)(rlA & 7) << 4;
    const uint32_t bXor = (uint32_t)(rlB & 7) << 4;

    float acc[4][4][4];
#pragma unroll
    for (int i = 0; i < 4; i++)
#pragma unroll
        for (int j = 0; j < 4; j++)
#pragma unroll
            for (int r = 0; r < 4; r++) acc[i][j][r] = 0.f;

    // issue one chunk's copies into buffer buf (src k-offset kt, in bf16 elems)
    auto issue = [&](int buf, int kt) {
        const uint32_t stb = sb + buf * GS_STAGE;
        const size_t so = (size_t)crow * Cc + kt + cpos * 8;
#pragma unroll
        for (int i = 0; i < 4; i++) {
            const size_t src = so + (size_t)(i * 32) * Cc;
            const uint32_t dst = coff0 + (uint32_t)(i * 32 * 128);
            cp16(stb + dst,         AHp + src);
            cp16(stb + 16384 + dst, ALp + src);
            cp16(stb + 32768 + dst, BHp + src);
            cp16(stb + 49152 + dst, BLp + src);
        }
    };

    issue(0, 0);  CP_COMMIT();
    issue(1, 64); CP_COMMIT();

    for (int c = 0; c < 12; c++) {
        if (c < 11) CP_WAIT(1); else CP_WAIT(0);
        __syncthreads();

        const uint32_t stb = sb + (c & 1) * GS_STAGE;
        const uint32_t sAh = stb, sAl = stb + 16384, sBh = stb + 32768, sBl = stb + 49152;
#pragma unroll
        for (int ks = 0; ks < 4; ks++) {
            const uint32_t ca = ((uint32_t)(ks * 32 + chA * 16)) ^ aXor;
            const uint32_t cbb = ((uint32_t)(ks * 32 + chB * 16)) ^ bXor;
            uint32_t Ah[4][4], Al[4][4], Bh[2][4], Bl[2][4];
#pragma unroll
            for (int mi = 0; mi < 4; mi++) {
                ldsm4(Ah[mi], sAh + aRow[mi] + ca);
                ldsm4(Al[mi], sAl + aRow[mi] + ca);
            }
#pragma unroll
            for (int j = 0; j < 2; j++) {
                ldsm4(Bh[j], sBh + bRow[j] + cbb);
                ldsm4(Bl[j], sBl + bRow[j] + cbb);
            }
#pragma unroll
            for (int mi = 0; mi < 4; mi++)
#pragma unroll
                for (int nj = 0; nj < 4; nj++) {
                    const uint32_t* bh = &Bh[nj >> 1][(nj & 1) * 2];
                    const uint32_t* bl = &Bl[nj >> 1][(nj & 1) * 2];
                    mma16816(acc[mi][nj], Ah[mi], bh);
                    mma16816(acc[mi][nj], Ah[mi], bl);
                    mma16816(acc[mi][nj], Al[mi], bh);
                }
        }
        __syncthreads();
        if (c < 10) { issue(c & 1, (c + 2) * 64); CP_COMMIT(); }
    }

    // ---- epilogue: bias + store
#pragma unroll
    for (int mi = 0; mi < 4; mi++) {
        int r0 = rb * 128 + m_warp + mi * 16 + (lane >> 2);
#pragma unroll
        for (int nj = 0; nj < 4; nj++) {
            int gc = cb * 128 + n_warp + nj * 8 + (lane & 3) * 2;
            float b0 = bias[gc], b1 = bias[gc + 1];
            float2 o0 = make_float2(acc[mi][nj][0] + b0, acc[mi][nj][1] + b1);
            float2 o1 = make_float2(acc[mi][nj][2] + b0, acc[mi][nj][3] + b1);
            *(float2*)(Y + (size_t)r0 * Cc + gc) = o0;
            *(float2*)(Y + (size_t)(r0 + 8) * Cc + gc) = o1;
        }
    }
}

// ======================= agent pooling =======================
__global__ void pool_agent(void)
{
    int b = blockIdx.x >> 4, a = blockIdx.x & 15;
    int c = threadIdx.x;
    const float* p = g_q + ((size_t)b * Nn + a * 256) * Cc + c;
    float s = 0.f;
#pragma unroll 8
    for (int i = 0; i < 256; i++) s += p[(size_t)i * Cc];
    g_agent[((size_t)b * Aa + a) * Cc + c] = s * (1.f / 256.f);
}

// ======================= group-of-16 reductions =======================
__device__ __forceinline__ float rmax16(float v) {
    v = fmaxf(v, __shfl_xor_sync(0xffffffffu, v, 8));
    v = fmaxf(v, __shfl_xor_sync(0xffffffffu, v, 4));
    v = fmaxf(v, __shfl_xor_sync(0xffffffffu, v, 2));
    v = fmaxf(v, __shfl_xor_sync(0xffffffffu, v, 1));
    return v;
}
__device__ __forceinline__ float rsum16(float v) {
    v += __shfl_xor_sync(0xffffffffu, v, 8);
    v += __shfl_xor_sync(0xffffffffu, v, 4);
    v += __shfl_xor_sync(0xffffffffu, v, 2);
    v += __shfl_xor_sync(0xffffffffu, v, 1);
    return v;
}

// ======================= stage 1: split-KV flash (agents -> keys) ========
__global__ __launch_bounds__(256) void stage1(void)
{
    const int h = blockIdx.x, b = blockIdx.y, sp = blockIdx.z;
    __shared__ float Ks[128][68];
    __shared__ float Vs[128][68];
    __shared__ float Ps[16][132];

    const int t = threadIdx.x;
    const int a = t >> 4, lx = t & 15;

    float4 qa[16];
    {
        const float* ap = g_agent + ((size_t)b * Aa + a) * Cc + h * HD;
#pragma unroll
        for (int i = 0; i < 16; i++) {
            float4 v = *(const float4*)(ap + i * 4);
            qa[i] = make_float4(v.x * 0.125f, v.y * 0.125f, v.z * 0.125f, v.w * 0.125f);
        }
    }

    float m_run = -1e30f, l_run = 0.f;
    float4 acc = make_float4(0.f, 0.f, 0.f, 0.f);
    const float* Kb = g_k + (size_t)b * Nn * Cc + h * HD;
    const float* Vb = g_v + (size_t)b * Nn * Cc + h * HD;

    const int m_beg = sp * (Nn / NSPLIT);
    for (int m0 = m_beg; m0 < m_beg + Nn / NSPLIT; m0 += 128) {
        __syncthreads();
#pragma unroll
        for (int u = 0; u < 8; u++) {
            int idx = t + u * 256;
            int r = idx >> 4, dq = idx & 15;
            ((float4*)&Ks[r][0])[dq] = *(const float4*)(Kb + (size_t)(m0 + r) * Cc + dq * 4);
            ((float4*)&Vs[r][0])[dq] = *(const float4*)(Vb + (size_t)(m0 + r) * Cc + dq * 4);
        }
        __syncthreads();

        float sv[8];
        float tmax = -1e30f;
#pragma unroll
        for (int jj = 0; jj < 8; jj++) {
            int j = lx + jj * 16;
            const float4* kr = (const float4*)&Ks[j][0];
            float4 s4 = make_float4(0.f, 0.f, 0.f, 0.f);
#pragma unroll
            for (int dq = 0; dq < 16; dq++) {
                float4 kv = kr[dq];
                s4.x += qa[dq].x * kv.x; s4.y += qa[dq].y * kv.y;
                s4.z += qa[dq].z * kv.z; s4.w += qa[dq].w * kv.w;
            }
            float s = (s4.x + s4.y) + (s4.z + s4.w);
            sv[jj] = s;
            tmax = fmaxf(tmax, s);
        }
        tmax = rmax16(tmax);
        float nm = fmaxf(m_run, tmax);
        float corr = __expf(m_run - nm);
        float ls = 0.f;
#pragma unroll
        for (int jj = 0; jj < 8; jj++) {
            float p = __expf(sv[jj] - nm);
            Ps[a][lx + jj * 16] = p;
            ls += p;
        }
        ls = rsum16(ls);
        l_run = l_run * corr + ls;
        m_run = nm;
        acc.x *= corr; acc.y *= corr; acc.z *= corr; acc.w *= corr;
        __syncwarp();
        for (int j = 0; j < 128; j++) {
            float p = Ps[a][j];
            float4 vv = ((const float4*)&Vs[j][0])[lx];
            acc.x += p * vv.x; acc.y += p * vv.y;
            acc.z += p * vv.z; acc.w += p * vv.w;
        }
    }
    const int pi = ((sp * Bb + b) * Hh + h) * Aa + a;
    if (lx == 0) { g_p1m[pi] = m_run; g_p1l[pi] = l_run; }
    *(float4*)&g_p1acc[(size_t)pi * HD + lx * 4] = acc;
}

__global__ void stage1_merge(void)
{
    const int bh = blockIdx.x;
    const int b = bh / Hh, h = bh % Hh;
    const int t = threadIdx.x;
    const int a = t >> 4, lx = t & 15;

    float ms[NSPLIT];
    float gm = -1e30f;
#pragma unroll
    for (int s = 0; s < NSPLIT; s++) {
        ms[s] = g_p1m[((s * Bb + b) * Hh + h) * Aa + a];
        gm = fmaxf(gm, ms[s]);
    }
    float L = 0.f;
    float4 acc = make_float4(0.f, 0.f, 0.f, 0.f);
#pragma unroll
    for (int s = 0; s < NSPLIT; s++) {
        int pi = ((s * Bb + b) * Hh + h) * Aa + a;
        float w = __expf(ms[s] - gm);
        L += g_p1l[pi] * w;
        float4 p = *(const float4*)&g_p1acc[(size_t)pi * HD + lx * 4];
        acc.x += w * p.x; acc.y += w * p.y; acc.z += w * p.z; acc.w += w * p.w;
    }
    float inv = 1.f / L;
    float4 o = make_float4(acc.x * inv, acc.y * inv, acc.z * inv, acc.w * inv);
    *(float4*)&g_agentv[(((size_t)b * Hh + h) * Aa + a) * HD + lx * 4] = o;
}

// ======================= stage 2 =======================
__global__ __launch_bounds__(384) void stage2(float* __restrict__ out)
{
    const int b = blockIdx.x;
    const int hg = blockIdx.z;
    __shared__ float ahh[6 * 16 * 64];
    __shared__ float agv[6 * 16 * 64];

    const int t = threadIdx.x;
    const int hl = t % 6;
    const int h = hg * 6 + hl;
    const int rl = t / 6;

    for (int i = t; i < 6 * 16 * 64; i += 384) {
        int d = i & 63, a = (i >> 6) & 15, hh = i >> 10;
        int hglob = hg * 6 + hh;
        ahh[i] = g_agent[((size_t)b * Aa + a) * Cc + hglob * HD + d];
        agv[i] = g_agentv[(((size_t)b * Hh + hglob) * Aa + a) * HD + d];
    }
    __syncthreads();

    float abv[16];
#pragma unroll
    for (int a = 0; a < 16; a++) abv[a] = g_ab[h * 16 + a];

    const int r0 = blockIdx.y * 256;
    for (int it = 0; it < 4; it++) {
        int r = r0 + it * 64 + rl;
        const float* qp = g_q + ((size_t)b * Nn + r) * Cc + h * HD;
        float4 q[16];
#pragma unroll
        for (int dq = 0; dq < 16; dq++) q[dq] = *(const float4*)(qp + dq * 4);

        float s[16];
        float smax = -1e30f;
#pragma unroll
        for (int a = 0; a < 16; a++) {
            const float4* ap = (const float4*)&ahh[(hl * 16 + a) * 64];
            float4 s4 = make_float4(0.f, 0.f, 0.f, 0.f);
#pragma unroll
            for (int dq = 0; dq < 16; dq++) {
                float4 av = ap[dq];
                s4.x += q[dq].x * av.x; s4.y += q[dq].y * av.y;
                s4.z += q[dq].z * av.z; s4.w += q[dq].w * av.w;
            }
            float sc = ((s4.x + s4.y) + (s4.z + s4.w)) * 0.125f + abv[a];
            s[a] = sc;
            smax = fmaxf(smax, sc);
        }
        float ssum = 0.f;
#pragma unroll
        for (int a = 0; a < 16; a++) { s[a] = __expf(s[a] - smax); ssum += s[a]; }
        float inv = 1.f / ssum;

        float4 o[16];
#pragma unroll
        for (int dq = 0; dq < 16; dq++) o[dq] = make_float4(0.f, 0.f, 0.f, 0.f);
#pragma unroll
        for (int a = 0; a < 16; a++) {
            float p = s[a] * inv;
            const float4* vp = (const float4*)&agv[(hl * 16 + a) * 64];
#pragma unroll
            for (int dq = 0; dq < 16; dq++) {
                float4 av = vp[dq];
                o[dq].x += p * av.x; o[dq].y += p * av.y;
                o[dq].z += p * av.z; o[dq].w += p * av.w;
            }
        }
        float* op = out + ((size_t)b * Nn + r) * Cc + h * HD;
#pragma unroll
        for (int dq = 0; dq < 16; dq++) *(float4*)(op + dq * 4) = o[dq];
    }
}

// ======================= launch =======================
extern "C" void kernel_launch(void* const* d_in, const int* in_sizes, int n_in,
                              void* d_out, int out_size)
{
    const float* s1 = (const float*)d_in[0];
    const float* s2 = (const float*)d_in[1];
    const float* Wq = (const float*)d_in[2];
    const float* bq = (const float*)d_in[3];
    const float* Wk = (const float*)d_in[4];
    const float* bk = (const float*)d_in[5];
    const float* Wv = (const float*)d_in[6];
    const float* bv = (const float*)d_in[7];
    const float* na = (const float*)d_in[9];
    const float* ha = (const float*)d_in[12];
    const float* wa = (const float*)d_in[13];
    float* out = (float*)d_out;

    cudaFuncSetAttribute(gemm_hmma, cudaFuncAttributeMaxDynamicSharedMemorySize, GS_TOTAL);

    bias_ab_kernel<<<1, 256>>>(na, ha, wa);
    convert_w<<<1728, 256>>>(Wq, Wk, Wv);
    presplit_x<<<12288, 256>>>(s1, s2);

    dim3 gg(Cc / 128, (Bb * Nn) / 128, 3);   // (6, 256, 3)
    gemm_hmma<<<gg, 256, GS_TOTAL>>>(bq, bk, bv);

    pool_agent<<<Bb * Aa, Cc>>>();
    stage1<<<dim3(Hh, Bb, NSPLIT), 256>>>();
    stage1_merge<<<Bb * Hh, 256>>>();
    stage2<<<dim3(Bb, 16, 2), 384>>>(out);
}

// round 7
// speedup vs baseline: 2.2565x; 1.0424x over previous
#include <cuda_runtime.h>
#include <cuda_bf16.h>
#include <math.h>
#include <stdint.h>

#define Hh 12
#define Aa 16
#define Cc 768
#define HD 64
#define Bb 8
#define Nn 4096

// ======================= helpers =======================
__device__ __forceinline__ uint32_t smem_u32(const void* p) {
    uint32_t a;
    asm("{ .reg .u64 t; cvta.to.shared.u64 t, %1; cvt.u32.u64 %0, t; }" : "=r"(a) : "l"(p));
    return a;
}

#define SMEM_SWIZZLE_128B(off) ((off) ^ (((off) >> 3) & 0x70))

__device__ __forceinline__ void ldsm4(uint32_t* r, uint32_t a) {
    asm volatile("ldmatrix.sync.aligned.m8n8.x4.shared.b16 {%0,%1,%2,%3}, [%4];"
                 : "=r"(r[0]), "=r"(r[1]), "=r"(r[2]), "=r"(r[3]) : "r"(a));
}
__device__ __forceinline__ void mma16816(float* c, const uint32_t* a, const uint32_t* b) {
    asm volatile(
        "mma.sync.aligned.m16n8k16.row.col.f32.bf16.bf16.f32 "
        "{%0,%1,%2,%3}, {%4,%5,%6,%7}, {%8,%9}, {%0,%1,%2,%3};"
        : "+f"(c[0]), "+f"(c[1]), "+f"(c[2]), "+f"(c[3])
        : "r"(a[0]), "r"(a[1]), "r"(a[2]), "r"(a[3]), "r"(b[0]), "r"(b[1]));
}
__device__ __forceinline__ void cp16(uint32_t dst, const void* src) {
    asm volatile("cp.async.cg.shared.global [%0], [%1], 16;" :: "r"(dst), "l"(src));
}
#define CP_COMMIT() asm volatile("cp.async.commit_group;" ::: "memory")
#define CP_WAIT(n)  asm volatile("cp.async.wait_group %0;" :: "n"(n) : "memory")

// ======================= device scratch =======================
__device__ __align__(16) float g_q[(size_t)Bb * Nn * Cc];
__device__ __align__(16) float g_k[(size_t)Bb * Nn * Cc];
__device__ __align__(16) float g_v[(size_t)Bb * Nn * Cc];
__device__ __align__(16) float g_agent[(size_t)Bb * Aa * Cc];
__device__ __align__(16) float g_agentv[(size_t)Bb * Hh * Aa * HD];
__device__ float g_ab[Hh * Aa];
__device__ __align__(16) __nv_bfloat16 g_w_hi[3 * Cc * Cc];
__device__ __align__(16) __nv_bfloat16 g_w_lo[3 * Cc * Cc];
__device__ __align__(16) __nv_bfloat16 g_x1h[(size_t)Bb * Nn * Cc];
__device__ __align__(16) __nv_bfloat16 g_x1l[(size_t)Bb * Nn * Cc];
__device__ __align__(16) __nv_bfloat16 g_x2h[(size_t)Bb * Nn * Cc];
__device__ __align__(16) __nv_bfloat16 g_x2l[(size_t)Bb * Nn * Cc];
#define NSPLIT 8
__device__ float g_p1m[NSPLIT * Bb * Hh * Aa];
__device__ float g_p1l[NSPLIT * Bb * Hh * Aa];
__device__ __align__(16) float g_p1acc[(size_t)NSPLIT * Bb * Hh * Aa * HD];

// ======================= fp32 -> bf16 hi/lo split =======================
__device__ __forceinline__ void split4(float4 x, uint2& hi, uint2& lo) {
    __nv_bfloat162 h01 = __floats2bfloat162_rn(x.x, x.y);
    __nv_bfloat162 h23 = __floats2bfloat162_rn(x.z, x.w);
    uint32_t u01 = *reinterpret_cast<uint32_t*>(&h01);
    uint32_t u23 = *reinterpret_cast<uint32_t*>(&h23);
    float lx = x.x - __uint_as_float(u01 << 16);
    float ly = x.y - __uint_as_float(u01 & 0xffff0000u);
    float lz = x.z - __uint_as_float(u23 << 16);
    float lw = x.w - __uint_as_float(u23 & 0xffff0000u);
    __nv_bfloat162 l01 = __floats2bfloat162_rn(lx, ly);
    __nv_bfloat162 l23 = __floats2bfloat162_rn(lz, lw);
    hi = make_uint2(u01, u23);
    lo = make_uint2(*reinterpret_cast<uint32_t*>(&l01), *reinterpret_cast<uint32_t*>(&l23));
}

// ======================= prep: weight split + ab bias (fused) ===========
__global__ void prep_kernel(const float* __restrict__ Wq, const float* __restrict__ Wk,
                            const float* __restrict__ Wv, const float* __restrict__ na,
                            const float* __restrict__ ha, const float* __restrict__ wa)
{
    if (blockIdx.x < 1728) {
        int idx = blockIdx.x * 256 + threadIdx.x;
        int w = idx / 147456;
        int r = idx - w * 147456;
        const float* src = (w == 0) ? Wq : ((w == 1) ? Wk : Wv);
        uint2 hi, lo;
        split4(*(const float4*)(src + (size_t)r * 4), hi, lo);
        *(uint2*)&g_w_hi[(size_t)idx * 4] = hi;
        *(uint2*)&g_w_lo[(size_t)idx * 4] = lo;
        return;
    }
    // ---- ab bias branch (1 block) ----
    int t = threadIdx.x;
    if (t >= Hh * Aa) return;
    int h = t >> 4, a = t & 15;
    float Wt[7];
#pragma unroll
    for (int i = 0; i < 7; i++) Wt[i] = 0.f;
    for (int o = 0; o < 16; o++) {
        float x = (o + 0.5f) * (7.0f / 16.0f) - 0.5f;
        float fx = floorf(x);
        int i0 = (int)fx;
        float f = x - fx;
        if (i0 < 0)       Wt[0] += 1.f;
        else if (i0 >= 6) Wt[6] += 1.f;
        else { Wt[i0] += 1.f - f; Wt[i0 + 1] += f; }
    }
    float s = 0.f;
    const float* np = na + (size_t)t * 49;
#pragma unroll
    for (int i = 0; i < 7; i++)
#pragma unroll
        for (int j = 0; j < 7; j++)
            s += Wt[i] * Wt[j] * np[i * 7 + j];
    float sh = 0.f, sw = 0.f;
#pragma unroll
    for (int i = 0; i < 16; i++) {
        sh += ha[(h * 16 + i) * 16 + a];
        sw += wa[(h * 16 + i) * 16 + a];
    }
    g_ab[t] = s * (1.f / 256.f) + (sh + sw) * (1.f / 16.f);
}

// ======================= activation pre-split =======================
__global__ void presplit_x(const float* __restrict__ s1, const float* __restrict__ s2)
{
    const size_t PER = (size_t)Bb * Nn * Cc / 4;
    size_t base = (size_t)blockIdx.x * 1024 + threadIdx.x;
#pragma unroll
    for (int i = 0; i < 4; i++) {
        size_t idx = base + (size_t)i * 256;
        const float* src;
        __nv_bfloat16 *dh, *dl;
        size_t r;
        if (idx < PER) { src = s1; dh = g_x1h; dl = g_x1l; r = idx; }
        else           { src = s2; dh = g_x2h; dl = g_x2l; r = idx - PER; }
        uint2 hi, lo;
        split4(*(const float4*)(src + r * 4), hi, lo);
        *(uint2*)&dh[r * 4] = hi;
        *(uint2*)&dl[r * 4] = lo;
    }
}

// ======================= HMMA GEMM: 256x128 tile, fused agent pooling ====
// stage: Ahi 32K | Alo 32K | Bhi 16K | Blo 16K = 96K; x2 = 192K
#define GS_STAGE 98304
#define GS_TOTAL (2 * GS_STAGE)

__global__ __launch_bounds__(256, 1) void gemm_hmma(
    const float* __restrict__ bq, const float* __restrict__ bk,
    const float* __restrict__ bv)
{
    extern __shared__ char smem[];
    const uint32_t sb = smem_u32(smem);
    const int t = threadIdx.x, lane = t & 31, wid = t >> 5;
    const int rb = blockIdx.y, cb = blockIdx.x, sel = blockIdx.z;

    const __nv_bfloat16* XH = (sel == 0) ? g_x1h : g_x2h;
    const __nv_bfloat16* XL = (sel == 0) ? g_x1l : g_x2l;
    const __nv_bfloat16* WH = g_w_hi + (size_t)sel * Cc * Cc;
    const __nv_bfloat16* WL = g_w_lo + (size_t)sel * Cc * Cc;
    float* Y = (sel == 0) ? g_q : ((sel == 1) ? g_k : g_v);
    const float* bias = (sel == 0) ? bq : ((sel == 1) ? bk : bv);

    const __nv_bfloat16* AHp = XH + (size_t)rb * 256 * Cc;
    const __nv_bfloat16* ALp = XL + (size_t)rb * 256 * Cc;
    const __nv_bfloat16* BHp = WH + (size_t)cb * 128 * Cc;
    const __nv_bfloat16* BLp = WL + (size_t)cb * 128 * Cc;

    const int crow = t >> 3, cpos = t & 7;
    const uint32_t coff0 = SMEM_SWIZZLE_128B((uint32_t)(crow * 128 + cpos * 16));

    // warp grid: 4 m-groups x 2 n-groups, warp tile 64x64
    const int m_warp = (wid >> 1) * 64, n_warp = (wid & 1) * 64;
    const int rlA = (lane & 7) | (((lane >> 3) & 1) << 3);
    const int chA = lane >> 4;
    const int rlB = (lane & 7) | ((lane >> 4) << 3);
    const int chB = (lane >> 3) & 1;
    uint32_t aRow[4];
#pragma unroll
    for (int mi = 0; mi < 4; mi++)
        aRow[mi] = (uint32_t)(m_warp + mi * 16 + rlA) * 128;
    uint32_t bRow[4];
#pragma unroll
    for (int j = 0; j < 4; j++)
        bRow[j] = (uint32_t)(n_warp + j * 16 + rlB) * 128;
    const uint32_t aXor = (uint32_t)(rlA & 7) << 4;
    const uint32_t bXor = (uint32_t)(rlB & 7) << 4;

    float acc[4][8][4];
#pragma unroll
    for (int i = 0; i < 4; i++)
#pragma unroll
        for (int j = 0; j < 8; j++)
#pragma unroll
            for (int r = 0; r < 4; r++) acc[i][j][r] = 0.f;

    auto issue = [&](int buf, int kt) {
        const uint32_t stb = sb + buf * GS_STAGE;
        const size_t so = (size_t)crow * Cc + kt + cpos * 8;
#pragma unroll
        for (int i = 0; i < 8; i++) {
            const size_t src = so + (size_t)(i * 32) * Cc;
            const uint32_t dst = coff0 + (uint32_t)(i * 32 * 128);
            cp16(stb + dst,         AHp + src);
            cp16(stb + 32768 + dst, ALp + src);
        }
#pragma unroll
        for (int i = 0; i < 4; i++) {
            const size_t src = so + (size_t)(i * 32) * Cc;
            const uint32_t dst = coff0 + (uint32_t)(i * 32 * 128);
            cp16(stb + 65536 + dst, BHp + src);
            cp16(stb + 81920 + dst, BLp + src);
        }
    };

    issue(0, 0);  CP_COMMIT();
    issue(1, 64); CP_COMMIT();

    for (int c = 0; c < 12; c++) {
        if (c < 11) CP_WAIT(1); else CP_WAIT(0);
        __syncthreads();

        const uint32_t stb = sb + (c & 1) * GS_STAGE;
        const uint32_t sAh = stb, sAl = stb + 32768, sBh = stb + 65536, sBl = stb + 81920;
#pragma unroll
        for (int ks = 0; ks < 4; ks++) {
            const uint32_t ca = ((uint32_t)(ks * 32 + chA * 16)) ^ aXor;
            const uint32_t cbb = ((uint32_t)(ks * 32 + chB * 16)) ^ bXor;
            uint32_t Ah[4][4], Al[4][4], Bh[4][4], Bl[4][4];
#pragma unroll
            for (int mi = 0; mi < 4; mi++) {
                ldsm4(Ah[mi], sAh + aRow[mi] + ca);
                ldsm4(Al[mi], sAl + aRow[mi] + ca);
            }
#pragma unroll
            for (int j = 0; j < 4; j++) {
                ldsm4(Bh[j], sBh + bRow[j] + cbb);
                ldsm4(Bl[j], sBl + bRow[j] + cbb);
            }
#pragma unroll
            for (int mi = 0; mi < 4; mi++)
#pragma unroll
                for (int nj = 0; nj < 8; nj++) {
                    const uint32_t* bh = &Bh[nj >> 1][(nj & 1) * 2];
                    const uint32_t* bl = &Bl[nj >> 1][(nj & 1) * 2];
                    mma16816(acc[mi][nj], Ah[mi], bh);
                    mma16816(acc[mi][nj], Ah[mi], bl);
                    mma16816(acc[mi][nj], Al[mi], bh);
                }
        }
        __syncthreads();
        if (c < 10) { issue(c & 1, (c + 2) * 64); CP_COMMIT(); }
    }

    // ---- epilogue: bias + store
#pragma unroll
    for (int mi = 0; mi < 4; mi++) {
        int r0 = rb * 256 + m_warp + mi * 16 + (lane >> 2);
#pragma unroll
        for (int nj = 0; nj < 8; nj++) {
            int gc = cb * 128 + n_warp + nj * 8 + (lane & 3) * 2;
            float b0 = bias[gc], b1 = bias[gc + 1];
            float2 o0 = make_float2(acc[mi][nj][0] + b0, acc[mi][nj][1] + b1);
            float2 o1 = make_float2(acc[mi][nj][2] + b0, acc[mi][nj][3] + b1);
            *(float2*)(Y + (size_t)r0 * Cc + gc) = o0;
            *(float2*)(Y + (size_t)(r0 + 8) * Cc + gc) = o1;
        }
    }

    // ---- fused agent pooling (sel==0 only): this CTA's 256 rows = one agent
    if (sel == 0) {
        float cs[16];
#pragma unroll
        for (int nj = 0; nj < 8; nj++) {
            float s0 = 0.f, s1v = 0.f;
#pragma unroll
            for (int mi = 0; mi < 4; mi++) {
                s0  += acc[mi][nj][0] + acc[mi][nj][2];
                s1v += acc[mi][nj][1] + acc[mi][nj][3];
            }
            cs[nj * 2] = s0;
            cs[nj * 2 + 1] = s1v;
        }
#pragma unroll
        for (int off = 4; off < 32; off <<= 1)
#pragma unroll
            for (int k = 0; k < 16; k++)
                cs[k] += __shfl_xor_sync(0xffffffffu, cs[k], off);

        float* red = (float*)smem;   // [8 wid][4 lane][16]
        __syncthreads();
        if (lane < 4) {
#pragma unroll
            for (int k = 0; k < 16; k++)
                red[(wid * 4 + lane) * 16 + k] = cs[k];
        }
        __syncthreads();
        if (t < 128) {
            int c = t;
            int hi = (c >= 64) ? 1 : 0;
            int cloc = c & 63;
            int nj = cloc >> 3, l2 = (cloc >> 1) & 3, k = nj * 2 + (cloc & 1);
            float sum = 0.f;
#pragma unroll
            for (int g = 0; g < 4; g++)
                sum += red[((g * 2 + hi) * 4 + l2) * 16 + k];
            int b = rb >> 4, a = rb & 15;
            g_agent[((size_t)b * Aa + a) * Cc + cb * 128 + c] =
                sum * (1.f / 256.f) + bias[cb * 128 + c];
        }
    }
}

// ======================= group-of-16 reductions =======================
__device__ __forceinline__ float rmax16(float v) {
    v = fmaxf(v, __shfl_xor_sync(0xffffffffu, v, 8));
    v = fmaxf(v, __shfl_xor_sync(0xffffffffu, v, 4));
    v = fmaxf(v, __shfl_xor_sync(0xffffffffu, v, 2));
    v = fmaxf(v, __shfl_xor_sync(0xffffffffu, v, 1));
    return v;
}
__device__ __forceinline__ float rsum16(float v) {
    v += __shfl_xor_sync(0xffffffffu, v, 8);
    v += __shfl_xor_sync(0xffffffffu, v, 4);
    v += __shfl_xor_sync(0xffffffffu, v, 2);
    v += __shfl_xor_sync(0xffffffffu, v, 1);
    return v;
}

// ======================= stage 1: split-KV flash (agents -> keys) ========
__global__ __launch_bounds__(256) void stage1(void)
{
    const int h = blockIdx.x, b = blockIdx.y, sp = blockIdx.z;
    __shared__ float Ks[128][68];
    __shared__ float Vs[128][68];
    __shared__ float Ps[16][132];

    const int t = threadIdx.x;
    const int a = t >> 4, lx = t & 15;

    float4 qa[16];
    {
        const float* ap = g_agent + ((size_t)b * Aa + a) * Cc + h * HD;
#pragma unroll
        for (int i = 0; i < 16; i++) {
            float4 v = *(const float4*)(ap + i * 4);
            qa[i] = make_float4(v.x * 0.125f, v.y * 0.125f, v.z * 0.125f, v.w * 0.125f);
        }
    }

    float m_run = -1e30f, l_run = 0.f;
    float4 acc = make_float4(0.f, 0.f, 0.f, 0.f);
    const float* Kb = g_k + (size_t)b * Nn * Cc + h * HD;
    const float* Vb = g_v + (size_t)b * Nn * Cc + h * HD;

    const int m_beg = sp * (Nn / NSPLIT);
    for (int m0 = m_beg; m0 < m_beg + Nn / NSPLIT; m0 += 128) {
        __syncthreads();
#pragma unroll
        for (int u = 0; u < 8; u++) {
            int idx = t + u * 256;
            int r = idx >> 4, dq = idx & 15;
            ((float4*)&Ks[r][0])[dq] = *(const float4*)(Kb + (size_t)(m0 + r) * Cc + dq * 4);
            ((float4*)&Vs[r][0])[dq] = *(const float4*)(Vb + (size_t)(m0 + r) * Cc + dq * 4);
        }
        __syncthreads();

        float sv[8];
        float tmax = -1e30f;
#pragma unroll
        for (int jj = 0; jj < 8; jj++) {
            int j = lx + jj * 16;
            const float4* kr = (const float4*)&Ks[j][0];
            float4 s4 = make_float4(0.f, 0.f, 0.f, 0.f);
#pragma unroll
            for (int dq = 0; dq < 16; dq++) {
                float4 kv = kr[dq];
                s4.x += qa[dq].x * kv.x; s4.y += qa[dq].y * kv.y;
                s4.z += qa[dq].z * kv.z; s4.w += qa[dq].w * kv.w;
            }
            float s = (s4.x + s4.y) + (s4.z + s4.w);
            sv[jj] = s;
            tmax = fmaxf(tmax, s);
        }
        tmax = rmax16(tmax);
        float nm = fmaxf(m_run, tmax);
        float corr = __expf(m_run - nm);
        float ls = 0.f;
#pragma unroll
        for (int jj = 0; jj < 8; jj++) {
            float p = __expf(sv[jj] - nm);
            Ps[a][lx + jj * 16] = p;
            ls += p;
        }
        ls = rsum16(ls);
        l_run = l_run * corr + ls;
        m_run = nm;
        acc.x *= corr; acc.y *= corr; acc.z *= corr; acc.w *= corr;
        __syncwarp();
#pragma unroll 8
        for (int j = 0; j < 128; j++) {
            float p = Ps[a][j];
            float4 vv = ((const float4*)&Vs[j][0])[lx];
            acc.x += p * vv.x; acc.y += p * vv.y;
            acc.z += p * vv.z; acc.w += p * vv.w;
        }
    }
    const int pi = ((sp * Bb + b) * Hh + h) * Aa + a;
    if (lx == 0) { g_p1m[pi] = m_run; g_p1l[pi] = l_run; }
    *(float4*)&g_p1acc[(size_t)pi * HD + lx * 4] = acc;
}

__global__ void stage1_merge(void)
{
    const int bh = blockIdx.x;
    const int b = bh / Hh, h = bh % Hh;
    const int t = threadIdx.x;
    const int a = t >> 4, lx = t & 15;

    float ms[NSPLIT];
    float gm = -1e30f;
#pragma unroll
    for (int s = 0; s < NSPLIT; s++) {
        ms[s] = g_p1m[((s * Bb + b) * Hh + h) * Aa + a];
        gm = fmaxf(gm, ms[s]);
    }
    float L = 0.f;
    float4 acc = make_float4(0.f, 0.f, 0.f, 0.f);
#pragma unroll
    for (int s = 0; s < NSPLIT; s++) {
        int pi = ((s * Bb + b) * Hh + h) * Aa + a;
        float w = __expf(ms[s] - gm);
        L += g_p1l[pi] * w;
        float4 p = *(const float4*)&g_p1acc[(size_t)pi * HD + lx * 4];
        acc.x += w * p.x; acc.y += w * p.y; acc.z += w * p.z; acc.w += w * p.w;
    }
    float inv = 1.f / L;
    float4 o = make_float4(acc.x * inv, acc.y * inv, acc.z * inv, acc.w * inv);
    *(float4*)&g_agentv[(((size_t)b * Hh + h) * Aa + a) * HD + lx * 4] = o;
}

// ======================= stage 2 =======================
__global__ __launch_bounds__(384) void stage2(float* __restrict__ out)
{
    const int b = blockIdx.x;
    const int hg = blockIdx.z;
    __shared__ float ahh[6 * 16 * 64];
    __shared__ float agv[6 * 16 * 64];

    const int t = threadIdx.x;
    const int hl = t % 6;
    const int h = hg * 6 + hl;
    const int rl = t / 6;

    for (int i = t; i < 6 * 16 * 64; i += 384) {
        int d = i & 63, a = (i >> 6) & 15, hh = i >> 10;
        int hglob = hg * 6 + hh;
        ahh[i] = g_agent[((size_t)b * Aa + a) * Cc + hglob * HD + d];
        agv[i] = g_agentv[(((size_t)b * Hh + hglob) * Aa + a) * HD + d];
    }
    __syncthreads();

    float abv[16];
#pragma unroll
    for (int a = 0; a < 16; a++) abv[a] = g_ab[h * 16 + a];

    const int r0 = blockIdx.y * 256;
    for (int it = 0; it < 4; it++) {
        int r = r0 + it * 64 + rl;
        const float* qp = g_q + ((size_t)b * Nn + r) * Cc + h * HD;
        float4 q[16];
#pragma unroll
        for (int dq = 0; dq < 16; dq++) q[dq] = *(const float4*)(qp + dq * 4);

        float s[16];
        float smax = -1e30f;
#pragma unroll
        for (int a = 0; a < 16; a++) {
            const float4* ap = (const float4*)&ahh[(hl * 16 + a) * 64];
            float4 s4 = make_float4(0.f, 0.f, 0.f, 0.f);
#pragma unroll
            for (int dq = 0; dq < 16; dq++) {
                float4 av = ap[dq];
                s4.x += q[dq].x * av.x; s4.y += q[dq].y * av.y;
                s4.z += q[dq].z * av.z; s4.w += q[dq].w * av.w;
            }
            float sc = ((s4.x + s4.y) + (s4.z + s4.w)) * 0.125f + abv[a];
            s[a] = sc;
            smax = fmaxf(smax, sc);
        }
        float ssum = 0.f;
#pragma unroll
        for (int a = 0; a < 16; a++) { s[a] = __expf(s[a] - smax); ssum += s[a]; }
        float inv = 1.f / ssum;

        float4 o[16];
#pragma unroll
        for (int dq = 0; dq < 16; dq++) o[dq] = make_float4(0.f, 0.f, 0.f, 0.f);
#pragma unroll
        for (int a = 0; a < 16; a++) {
            float p = s[a] * inv;
            const float4* vp = (const float4*)&agv[(hl * 16 + a) * 64];
#pragma unroll
            for (int dq = 0; dq < 16; dq++) {
                float4 av = vp[dq];
                o[dq].x += p * av.x; o[dq].y += p * av.y;
                o[dq].z += p * av.z; o[dq].w += p * av.w;
            }
        }
        float* op = out + ((size_t)b * Nn + r) * Cc + h * HD;
#pragma unroll
        for (int dq = 0; dq < 16; dq++) *(float4*)(op + dq * 4) = o[dq];
    }
}

// ======================= launch =======================
extern "C" void kernel_launch(void* const* d_in, const int* in_sizes, int n_in,
                              void* d_out, int out_size)
{
    const float* s1 = (const float*)d_in[0];
    const float* s2 = (const float*)d_in[1];
    const float* Wq = (const float*)d_in[2];
    const float* bq = (const float*)d_in[3];
    const float* Wk = (const float*)d_in[4];
    const float* bk = (const float*)d_in[5];
    const float* Wv = (const float*)d_in[6];
    const float* bv = (const float*)d_in[7];
    const float* na = (const float*)d_in[9];
    const float* ha = (const float*)d_in[12];
    const float* wa = (const float*)d_in[13];
    float* out = (float*)d_out;

    cudaFuncSetAttribute(gemm_hmma, cudaFuncAttributeMaxDynamicSharedMemorySize, GS_TOTAL);

    prep_kernel<<<1729, 256>>>(Wq, Wk, Wv, na, ha, wa);
    presplit_x<<<12288, 256>>>(s1, s2);

    dim3 gg(Cc / 128, (Bb * Nn) / 256, 3);   // (6, 128, 3)
    gemm_hmma<<<gg, 256, GS_TOTAL>>>(bq, bk, bv);

    stage1<<<dim3(Hh, Bb, NSPLIT), 256>>>();   // <- profiled slot (launch idx 3)
    stage1_merge<<<Bb * Hh, 256>>>();
    stage2<<<dim3(Bb, 16, 2), 384>>>(out);
}

// round 8
// speedup vs baseline: 3.0650x; 1.3583x over previous
#include <cuda_runtime.h>
#include <cuda_bf16.h>
#include <math.h>
#include <stdint.h>

#define Hh 12
#define Aa 16
#define Cc 768
#define HD 64
#define Bb 8
#define Nn 4096

// ======================= helpers =======================
__device__ __forceinline__ uint32_t smem_u32(const void* p) {
    uint32_t a;
    asm("{ .reg .u64 t; cvta.to.shared.u64 t, %1; cvt.u32.u64 %0, t; }" : "=r"(a) : "l"(p));
    return a;
}

#define SMEM_SWIZZLE_128B(off) ((off) ^ (((off) >> 3) & 0x70))

__device__ __forceinline__ void ldsm4(uint32_t* r, uint32_t a) {
    asm volatile("ldmatrix.sync.aligned.m8n8.x4.shared.b16 {%0,%1,%2,%3}, [%4];"
                 : "=r"(r[0]), "=r"(r[1]), "=r"(r[2]), "=r"(r[3]) : "r"(a));
}
__device__ __forceinline__ void mma16816(float* c, const uint32_t* a, const uint32_t* b) {
    asm volatile(
        "mma.sync.aligned.m16n8k16.row.col.f32.bf16.bf16.f32 "
        "{%0,%1,%2,%3}, {%4,%5,%6,%7}, {%8,%9}, {%0,%1,%2,%3};"
        : "+f"(c[0]), "+f"(c[1]), "+f"(c[2]), "+f"(c[3])
        : "r"(a[0]), "r"(a[1]), "r"(a[2]), "r"(a[3]), "r"(b[0]), "r"(b[1]));
}
__device__ __forceinline__ void cp16(uint32_t dst, const void* src) {
    asm volatile("cp.async.cg.shared.global [%0], [%1], 16;" :: "r"(dst), "l"(src));
}
#define CP_COMMIT() asm volatile("cp.async.commit_group;" ::: "memory")
#define CP_WAIT(n)  asm volatile("cp.async.wait_group %0;" :: "n"(n) : "memory")

// ======================= device scratch =======================
__device__ __align__(16) float g_q[(size_t)Bb * Nn * Cc];
__device__ __align__(16) float g_k[(size_t)Bb * Nn * Cc];
__device__ __align__(16) float g_v[(size_t)Bb * Nn * Cc];
__device__ __align__(16) float g_agent[(size_t)Bb * Aa * Cc];
__device__ __align__(16) float g_agentv[(size_t)Bb * Hh * Aa * HD];
__device__ float g_ab[Hh * Aa];
__device__ __align__(16) __nv_bfloat16 g_w_hi[3 * Cc * Cc];
__device__ __align__(16) __nv_bfloat16 g_w_lo[3 * Cc * Cc];
__device__ __align__(16) __nv_bfloat16 g_x1h[(size_t)Bb * Nn * Cc];
__device__ __align__(16) __nv_bfloat16 g_x1l[(size_t)Bb * Nn * Cc];
__device__ __align__(16) __nv_bfloat16 g_x2h[(size_t)Bb * Nn * Cc];
__device__ __align__(16) __nv_bfloat16 g_x2l[(size_t)Bb * Nn * Cc];
#define NSPLIT 8
__device__ float g_p1m[NSPLIT * Bb * Hh * Aa];
__device__ float g_p1l[NSPLIT * Bb * Hh * Aa];
__device__ __align__(16) float g_p1acc[(size_t)NSPLIT * Bb * Hh * Aa * HD];

// ======================= fp32 -> bf16 hi/lo split =======================
__device__ __forceinline__ void split4(float4 x, uint2& hi, uint2& lo) {
    __nv_bfloat162 h01 = __floats2bfloat162_rn(x.x, x.y);
    __nv_bfloat162 h23 = __floats2bfloat162_rn(x.z, x.w);
    uint32_t u01 = *reinterpret_cast<uint32_t*>(&h01);
    uint32_t u23 = *reinterpret_cast<uint32_t*>(&h23);
    float lx = x.x - __uint_as_float(u01 << 16);
    float ly = x.y - __uint_as_float(u01 & 0xffff0000u);
    float lz = x.z - __uint_as_float(u23 << 16);
    float lw = x.w - __uint_as_float(u23 & 0xffff0000u);
    __nv_bfloat162 l01 = __floats2bfloat162_rn(lx, ly);
    __nv_bfloat162 l23 = __floats2bfloat162_rn(lz, lw);
    hi = make_uint2(u01, u23);
    lo = make_uint2(*reinterpret_cast<uint32_t*>(&l01), *reinterpret_cast<uint32_t*>(&l23));
}

// ======================= bias_ab =======================
__global__ void bias_ab_kernel(const float* __restrict__ na,
                               const float* __restrict__ ha,
                               const float* __restrict__ wa)
{
    int t = threadIdx.x;
    if (t >= Hh * Aa) return;
    int h = t >> 4, a = t & 15;
    float Wt[7];
#pragma unroll
    for (int i = 0; i < 7; i++) Wt[i] = 0.f;
    for (int o = 0; o < 16; o++) {
        float x = (o + 0.5f) * (7.0f / 16.0f) - 0.5f;
        float fx = floorf(x);
        int i0 = (int)fx;
        float f = x - fx;
        if (i0 < 0)       Wt[0] += 1.f;
        else if (i0 >= 6) Wt[6] += 1.f;
        else { Wt[i0] += 1.f - f; Wt[i0 + 1] += f; }
    }
    float s = 0.f;
    const float* np = na + (size_t)t * 49;
#pragma unroll
    for (int i = 0; i < 7; i++)
#pragma unroll
        for (int j = 0; j < 7; j++)
            s += Wt[i] * Wt[j] * np[i * 7 + j];
    float sh = 0.f, sw = 0.f;
#pragma unroll
    for (int i = 0; i < 16; i++) {
        sh += ha[(h * 16 + i) * 16 + a];
        sw += wa[(h * 16 + i) * 16 + a];
    }
    g_ab[t] = s * (1.f / 256.f) + (sh + sw) * (1.f / 16.f);
}

// ======================= weight split =======================
__global__ void convert_w(const float* __restrict__ Wq, const float* __restrict__ Wk,
                          const float* __restrict__ Wv)
{
    int idx = blockIdx.x * 256 + threadIdx.x;
    int w = idx / 147456;
    int r = idx - w * 147456;
    const float* src = (w == 0) ? Wq : ((w == 1) ? Wk : Wv);
    uint2 hi, lo;
    split4(*(const float4*)(src + (size_t)r * 4), hi, lo);
    *(uint2*)&g_w_hi[(size_t)idx * 4] = hi;
    *(uint2*)&g_w_lo[(size_t)idx * 4] = lo;
}

// ======================= activation pre-split =======================
__global__ void presplit_x(const float* __restrict__ s1, const float* __restrict__ s2)
{
    const size_t PER = (size_t)Bb * Nn * Cc / 4;
    size_t base = (size_t)blockIdx.x * 1024 + threadIdx.x;
#pragma unroll
    for (int i = 0; i < 4; i++) {
        size_t idx = base + (size_t)i * 256;
        const float* src;
        __nv_bfloat16 *dh, *dl;
        size_t r;
        if (idx < PER) { src = s1; dh = g_x1h; dl = g_x1l; r = idx; }
        else           { src = s2; dh = g_x2h; dl = g_x2l; r = idx - PER; }
        uint2 hi, lo;
        split4(*(const float4*)(src + r * 4), hi, lo);
        *(uint2*)&dh[r * 4] = hi;
        *(uint2*)&dl[r * 4] = lo;
    }
}

// ======================= HMMA GEMM: 256x128 tile, fused agent pooling ====
#define GS_STAGE 98304
#define GS_TOTAL (2 * GS_STAGE)

__global__ __launch_bounds__(256, 1) void gemm_hmma(
    const float* __restrict__ bq, const float* __restrict__ bk,
    const float* __restrict__ bv)
{
    extern __shared__ char smem[];
    const uint32_t sb = smem_u32(smem);
    const int t = threadIdx.x, lane = t & 31, wid = t >> 5;
    const int rb = blockIdx.y, cb = blockIdx.x, sel = blockIdx.z;

    const __nv_bfloat16* XH = (sel == 0) ? g_x1h : g_x2h;
    const __nv_bfloat16* XL = (sel == 0) ? g_x1l : g_x2l;
    const __nv_bfloat16* WH = g_w_hi + (size_t)sel * Cc * Cc;
    const __nv_bfloat16* WL = g_w_lo + (size_t)sel * Cc * Cc;
    float* Y = (sel == 0) ? g_q : ((sel == 1) ? g_k : g_v);
    const float* bias = (sel == 0) ? bq : ((sel == 1) ? bk : bv);

    const __nv_bfloat16* AHp = XH + (size_t)rb * 256 * Cc;
    const __nv_bfloat16* ALp = XL + (size_t)rb * 256 * Cc;
    const __nv_bfloat16* BHp = WH + (size_t)cb * 128 * Cc;
    const __nv_bfloat16* BLp = WL + (size_t)cb * 128 * Cc;

    const int crow = t >> 3, cpos = t & 7;
    const uint32_t coff0 = SMEM_SWIZZLE_128B((uint32_t)(crow * 128 + cpos * 16));

    const int m_warp = (wid >> 1) * 64, n_warp = (wid & 1) * 64;
    const int rlA = (lane & 7) | (((lane >> 3) & 1) << 3);
    const int chA = lane >> 4;
    const int rlB = (lane & 7) | ((lane >> 4) << 3);
    const int chB = (lane >> 3) & 1;
    uint32_t aRow[4];
#pragma unroll
    for (int mi = 0; mi < 4; mi++)
        aRow[mi] = (uint32_t)(m_warp + mi * 16 + rlA) * 128;
    uint32_t bRow[4];
#pragma unroll
    for (int j = 0; j < 4; j++)
        bRow[j] = (uint32_t)(n_warp + j * 16 + rlB) * 128;
    const uint32_t aXor = (uint32_t)(rlA & 7) << 4;
    const uint32_t bXor = (uint32_t)(rlB & 7) << 4;

    float acc[4][8][4];
#pragma unroll
    for (int i = 0; i < 4; i++)
#pragma unroll
        for (int j = 0; j < 8; j++)
#pragma unroll
            for (int r = 0; r < 4; r++) acc[i][j][r] = 0.f;

    auto issue = [&](int buf, int kt) {
        const uint32_t stb = sb + buf * GS_STAGE;
        const size_t so = (size_t)crow * Cc + kt + cpos * 8;
#pragma unroll
        for (int i = 0; i < 8; i++) {
            const size_t src = so + (size_t)(i * 32) * Cc;
            const uint32_t dst = coff0 + (uint32_t)(i * 32 * 128);
            cp16(stb + dst,         AHp + src);
            cp16(stb + 32768 + dst, ALp + src);
        }
#pragma unroll
        for (int i = 0; i < 4; i++) {
            const size_t src = so + (size_t)(i * 32) * Cc;
            const uint32_t dst = coff0 + (uint32_t)(i * 32 * 128);
            cp16(stb + 65536 + dst, BHp + src);
            cp16(stb + 81920 + dst, BLp + src);
        }
    };

    issue(0, 0);  CP_COMMIT();
    issue(1, 64); CP_COMMIT();

    for (int c = 0; c < 12; c++) {
        if (c < 11) CP_WAIT(1); else CP_WAIT(0);
        __syncthreads();

        const uint32_t stb = sb + (c & 1) * GS_STAGE;
        const uint32_t sAh = stb, sAl = stb + 32768, sBh = stb + 65536, sBl = stb + 81920;
#pragma unroll
        for (int ks = 0; ks < 4; ks++) {
            const uint32_t ca = ((uint32_t)(ks * 32 + chA * 16)) ^ aXor;
            const uint32_t cbb = ((uint32_t)(ks * 32 + chB * 16)) ^ bXor;
            uint32_t Ah[4][4], Al[4][4], Bh[4][4], Bl[4][4];
#pragma unroll
            for (int mi = 0; mi < 4; mi++) {
                ldsm4(Ah[mi], sAh + aRow[mi] + ca);
                ldsm4(Al[mi], sAl + aRow[mi] + ca);
            }
#pragma unroll
            for (int j = 0; j < 4; j++) {
                ldsm4(Bh[j], sBh + bRow[j] + cbb);
                ldsm4(Bl[j], sBl + bRow[j] + cbb);
            }
#pragma unroll
            for (int mi = 0; mi < 4; mi++)
#pragma unroll
                for (int nj = 0; nj < 8; nj++) {
                    const uint32_t* bh = &Bh[nj >> 1][(nj & 1) * 2];
                    const uint32_t* bl = &Bl[nj >> 1][(nj & 1) * 2];
                    mma16816(acc[mi][nj], Ah[mi], bh);
                    mma16816(acc[mi][nj], Ah[mi], bl);
                    mma16816(acc[mi][nj], Al[mi], bh);
                }
        }
        __syncthreads();
        if (c < 10) { issue(c & 1, (c + 2) * 64); CP_COMMIT(); }
    }

#pragma unroll
    for (int mi = 0; mi < 4; mi++) {
        int r0 = rb * 256 + m_warp + mi * 16 + (lane >> 2);
#pragma unroll
        for (int nj = 0; nj < 8; nj++) {
            int gc = cb * 128 + n_warp + nj * 8 + (lane & 3) * 2;
            float b0 = bias[gc], b1 = bias[gc + 1];
            float2 o0 = make_float2(acc[mi][nj][0] + b0, acc[mi][nj][1] + b1);
            float2 o1 = make_float2(acc[mi][nj][2] + b0, acc[mi][nj][3] + b1);
            *(float2*)(Y + (size_t)r0 * Cc + gc) = o0;
            *(float2*)(Y + (size_t)(r0 + 8) * Cc + gc) = o1;
        }
    }

    // ---- fused agent pooling (sel==0): CTA's 256 rows = one agent
    if (sel == 0) {
        float cs[16];
#pragma unroll
        for (int nj = 0; nj < 8; nj++) {
            float s0 = 0.f, s1v = 0.f;
#pragma unroll
            for (int mi = 0; mi < 4; mi++) {
                s0  += acc[mi][nj][0] + acc[mi][nj][2];
                s1v += acc[mi][nj][1] + acc[mi][nj][3];
            }
            cs[nj * 2] = s0;
            cs[nj * 2 + 1] = s1v;
        }
#pragma unroll
        for (int off = 4; off < 32; off <<= 1)
#pragma unroll
            for (int k = 0; k < 16; k++)
                cs[k] += __shfl_xor_sync(0xffffffffu, cs[k], off);

        float* red = (float*)smem;
        __syncthreads();
        if (lane < 4) {
#pragma unroll
            for (int k = 0; k < 16; k++)
                red[(wid * 4 + lane) * 16 + k] = cs[k];
        }
        __syncthreads();
        if (t < 128) {
            int c = t;
            int hi = (c >= 64) ? 1 : 0;
            int cloc = c & 63;
            int nj = cloc >> 3, l2 = (cloc >> 1) & 3, k = nj * 2 + (cloc & 1);
            float sum = 0.f;
#pragma unroll
            for (int g = 0; g < 4; g++)
                sum += red[((g * 2 + hi) * 4 + l2) * 16 + k];
            int b = rb >> 4, a = rb & 15;
            g_agent[((size_t)b * Aa + a) * Cc + cb * 128 + c] =
                sum * (1.f / 256.f) + bias[cb * 128 + c];
        }
    }
}

// ======================= group-of-16 reductions =======================
__device__ __forceinline__ float rmax16(float v) {
    v = fmaxf(v, __shfl_xor_sync(0xffffffffu, v, 8));
    v = fmaxf(v, __shfl_xor_sync(0xffffffffu, v, 4));
    v = fmaxf(v, __shfl_xor_sync(0xffffffffu, v, 2));
    v = fmaxf(v, __shfl_xor_sync(0xffffffffu, v, 1));
    return v;
}
__device__ __forceinline__ float rsum16(float v) {
    v += __shfl_xor_sync(0xffffffffu, v, 8);
    v += __shfl_xor_sync(0xffffffffu, v, 4);
    v += __shfl_xor_sync(0xffffffffu, v, 2);
    v += __shfl_xor_sync(0xffffffffu, v, 1);
    return v;
}

// ======================= stage 1: split-KV flash =======================
__global__ __launch_bounds__(256) void stage1(void)
{
    const int h = blockIdx.x, b = blockIdx.y, sp = blockIdx.z;
    __shared__ float Ks[128][68];
    __shared__ float Vs[128][68];
    __shared__ float Ps[16][132];

    const int t = threadIdx.x;
    const int a = t >> 4, lx = t & 15;

    float4 qa[16];
    {
        const float* ap = g_agent + ((size_t)b * Aa + a) * Cc + h * HD;
#pragma unroll
        for (int i = 0; i < 16; i++) {
            float4 v = *(const float4*)(ap + i * 4);
            qa[i] = make_float4(v.x * 0.125f, v.y * 0.125f, v.z * 0.125f, v.w * 0.125f);
        }
    }

    float m_run = -1e30f, l_run = 0.f;
    float4 acc = make_float4(0.f, 0.f, 0.f, 0.f);
    const float* Kb = g_k + (size_t)b * Nn * Cc + h * HD;
    const float* Vb = g_v + (size_t)b * Nn * Cc + h * HD;

    const int m_beg = sp * (Nn / NSPLIT);
    for (int m0 = m_beg; m0 < m_beg + Nn / NSPLIT; m0 += 128) {
        __syncthreads();
#pragma unroll
        for (int u = 0; u < 8; u++) {
            int idx = t + u * 256;
            int r = idx >> 4, dq = idx & 15;
            ((float4*)&Ks[r][0])[dq] = *(const float4*)(Kb + (size_t)(m0 + r) * Cc + dq * 4);
            ((float4*)&Vs[r][0])[dq] = *(const float4*)(Vb + (size_t)(m0 + r) * Cc + dq * 4);
        }
        __syncthreads();

        float sv[8];
        float tmax = -1e30f;
#pragma unroll
        for (int jj = 0; jj < 8; jj++) {
            int j = lx + jj * 16;
            const float4* kr = (const float4*)&Ks[j][0];
            float4 s4 = make_float4(0.f, 0.f, 0.f, 0.f);
#pragma unroll
            for (int dq = 0; dq < 16; dq++) {
                float4 kv = kr[dq];
                s4.x += qa[dq].x * kv.x; s4.y += qa[dq].y * kv.y;
                s4.z += qa[dq].z * kv.z; s4.w += qa[dq].w * kv.w;
            }
            float s = (s4.x + s4.y) + (s4.z + s4.w);
            sv[jj] = s;
            tmax = fmaxf(tmax, s);
        }
        tmax = rmax16(tmax);
        float nm = fmaxf(m_run, tmax);
        float corr = __expf(m_run - nm);
        float ls = 0.f;
#pragma unroll
        for (int jj = 0; jj < 8; jj++) {
            float p = __expf(sv[jj] - nm);
            Ps[a][lx + jj * 16] = p;
            ls += p;
        }
        ls = rsum16(ls);
        l_run = l_run * corr + ls;
        m_run = nm;
        acc.x *= corr; acc.y *= corr; acc.z *= corr; acc.w *= corr;
        __syncwarp();
#pragma unroll 8
        for (int j = 0; j < 128; j++) {
            float p = Ps[a][j];
            float4 vv = ((const float4*)&Vs[j][0])[lx];
            acc.x += p * vv.x; acc.y += p * vv.y;
            acc.z += p * vv.z; acc.w += p * vv.w;
        }
    }
    const int pi = ((sp * Bb + b) * Hh + h) * Aa + a;
    if (lx == 0) { g_p1m[pi] = m_run; g_p1l[pi] = l_run; }
    *(float4*)&g_p1acc[(size_t)pi * HD + lx * 4] = acc;
}

__global__ void stage1_merge(void)
{
    const int bh = blockIdx.x;
    const int b = bh / Hh, h = bh % Hh;
    const int t = threadIdx.x;
    const int a = t >> 4, lx = t & 15;

    float ms[NSPLIT];
    float gm = -1e30f;
#pragma unroll
    for (int s = 0; s < NSPLIT; s++) {
        ms[s] = g_p1m[((s * Bb + b) * Hh + h) * Aa + a];
        gm = fmaxf(gm, ms[s]);
    }
    float L = 0.f;
    float4 acc = make_float4(0.f, 0.f, 0.f, 0.f);
#pragma unroll
    for (int s = 0; s < NSPLIT; s++) {
        int pi = ((s * Bb + b) * Hh + h) * Aa + a;
        float w = __expf(ms[s] - gm);
        L += g_p1l[pi] * w;
        float4 p = *(const float4*)&g_p1acc[(size_t)pi * HD + lx * 4];
        acc.x += w * p.x; acc.y += w * p.y; acc.z += w * p.z; acc.w += w * p.w;
    }
    float inv = 1.f / L;
    float4 o = make_float4(acc.x * inv, acc.y * inv, acc.z * inv, acc.w * inv);
    *(float4*)&g_agentv[(((size_t)b * Hh + h) * Aa + a) * HD + lx * 4] = o;
}

// ======================= stage 2: warp-per-row, coalesced ===============
// SMEM floats: ahh 12*16*68=13056 | agv 12*16*64=12288 | qbuf 8*768=6144 | ps 8*192=1536
#define S2_AHH   0
#define S2_AGV   13056
#define S2_QBUF  (13056 + 12288)
#define S2_PS    (13056 + 12288 + 6144)
#define S2_FLOATS (13056 + 12288 + 6144 + 1536)
#define S2_BYTES (S2_FLOATS * 4)

__global__ __launch_bounds__(256, 1) void stage2(float* __restrict__ out)
{
    extern __shared__ float sm2[];
    float* ahh  = sm2 + S2_AHH;
    float* agv  = sm2 + S2_AGV;
    float* qbuf = sm2 + S2_QBUF;
    float* ps   = sm2 + S2_PS;

    const int b = blockIdx.x, rblk = blockIdx.y;
    const int t = threadIdx.x, lane = t & 31, w = t >> 5;

    for (int i = t; i < Hh * Aa * HD; i += 256) {
        int d = i & 63, a = (i >> 6) & 15, h = i >> 10;
        ahh[(h * 16 + a) * 68 + d] = g_agent[((size_t)b * Aa + a) * Cc + h * HD + d];
        agv[(h * 16 + a) * 64 + d] =
            g_agentv[(((size_t)b * Hh + h) * Aa + a) * HD + d];
    }
    __syncthreads();

    float* qw = qbuf + w * 768;
    float* pw = ps + w * 192;
    const int hhalf = lane >> 4;
    const int aa = lane & 15;

    for (int rr = 0; rr < 4; rr++) {
        const int r = rblk * 32 + rr * 8 + w;
        const float* qp = g_q + ((size_t)b * Nn + r) * Cc;
#pragma unroll
        for (int j = 0; j < 6; j++)
            *(float4*)(qw + (lane + 32 * j) * 4) = *(const float4*)(qp + (lane + 32 * j) * 4);
        __syncwarp();

        // scores + softmax (half-warp handles one head per g)
#pragma unroll
        for (int g = 0; g < 6; g++) {
            const int h = g * 2 + hhalf;
            const float4* q4 = (const float4*)(qw + h * 64);
            const float4* a4 = (const float4*)(ahh + (h * 16 + aa) * 68);
            float4 s4 = make_float4(0.f, 0.f, 0.f, 0.f);
#pragma unroll
            for (int dq = 0; dq < 16; dq++) {
                float4 qv = q4[dq], av = a4[dq];
                s4.x += qv.x * av.x; s4.y += qv.y * av.y;
                s4.z += qv.z * av.z; s4.w += qv.w * av.w;
            }
            float s = ((s4.x + s4.y) + (s4.z + s4.w)) * 0.125f + g_ab[h * 16 + aa];
            float mx = rmax16(s);
            float p = __expf(s - mx);
            float sum = rsum16(p);
            pw[h * 16 + aa] = p / sum;
        }
        __syncwarp();

        // output: lane covers float4 elements e4 = lane + 32*j (coalesced)
        float* op = out + ((size_t)b * Nn + r) * Cc;
#pragma unroll
        for (int j = 0; j < 6; j++) {
            const int e4 = lane + 32 * j;
            const int h = e4 >> 4, d4 = e4 & 15;
            float4 o = make_float4(0.f, 0.f, 0.f, 0.f);
            const float* pv = pw + h * 16;
            const float4* v4 = (const float4*)agv + h * 16 * 16 + d4;
#pragma unroll
            for (int a = 0; a < 16; a++) {
                float p = pv[a];
                float4 vv = v4[a * 16];
                o.x += p * vv.x; o.y += p * vv.y;
                o.z += p * vv.z; o.w += p * vv.w;
            }
            *(float4*)(op + e4 * 4) = o;
        }
        __syncwarp();
    }
}

// ======================= launch =======================
extern "C" void kernel_launch(void* const* d_in, const int* in_sizes, int n_in,
                              void* d_out, int out_size)
{
    const float* s1 = (const float*)d_in[0];
    const float* s2 = (const float*)d_in[1];
    const float* Wq = (const float*)d_in[2];
    const float* bq = (const float*)d_in[3];
    const float* Wk = (const float*)d_in[4];
    const float* bk = (const float*)d_in[5];
    const float* Wv = (const float*)d_in[6];
    const float* bv = (const float*)d_in[7];
    const float* na = (const float*)d_in[9];
    const float* ha = (const float*)d_in[12];
    const float* wa = (const float*)d_in[13];
    float* out = (float*)d_out;

    cudaFuncSetAttribute(gemm_hmma, cudaFuncAttributeMaxDynamicSharedMemorySize, GS_TOTAL);
    cudaFuncSetAttribute(stage2, cudaFuncAttributeMaxDynamicSharedMemorySize, S2_BYTES);

    bias_ab_kernel<<<1, 256>>>(na, ha, wa);          // idx 0
    convert_w<<<1728, 256>>>(Wq, Wk, Wv);            // idx 1
    presplit_x<<<12288, 256>>>(s1, s2);              // idx 2

    dim3 gg(Cc / 128, (Bb * Nn) / 256, 3);
    gemm_hmma<<<gg, 256, GS_TOTAL>>>(bq, bk, bv);    // idx 3  <- profiled slot

    stage1<<<dim3(Hh, Bb, NSPLIT), 256>>>();         // idx 4
    stage1_merge<<<Bb * Hh, 256>>>();                // idx 5
    stage2<<<dim3(Bb, Nn / 32), 256, S2_BYTES>>>(out); // idx 6
}